// round 1
// baseline (speedup 1.0000x reference)
#include <cuda_runtime.h>

#define T_SEQ  4096
#define C_DIM  1024
#define H_NUM  16
#define D_HEAD 64
#define F_DIM  (3 * C_DIM)   // 3072

// Scratch (no allocations allowed): qkv [T, 3C], y [T, C]
__device__ float g_qkv[T_SEQ * F_DIM];
__device__ float g_y[T_SEQ * C_DIM];

// ---------------------------------------------------------------------------
// SGEMM NT: C[M,N] = sum_k A[m,k] * B[n,k]   (A: MxK row-major, B: NxK row-major)
// Matches einsum('btc,fc->btf'): both operands have K (=c) contiguous.
// BM=BN=128, BK=16, 256 threads, 8x8 microtile per thread.
// Shapes here are all multiples of the tiles, so no bounds checks.
// ---------------------------------------------------------------------------
template<int BM, int BN, int BK>
__device__ __forceinline__ void sgemm_nt_body(const float* __restrict__ A,
                                              const float* __restrict__ B,
                                              float* __restrict__ C,
                                              int M, int N, int K)
{
    __shared__ float As[BK][BM];
    __shared__ float Bs[BK][BN];

    const int tid = threadIdx.x;
    const int m0 = blockIdx.y * BM;
    const int n0 = blockIdx.x * BN;
    const int tx = tid % (BN / 8);   // 0..15
    const int ty = tid / (BN / 8);   // 0..15

    float acc[8][8];
#pragma unroll
    for (int i = 0; i < 8; i++)
#pragma unroll
        for (int j = 0; j < 8; j++) acc[i][j] = 0.f;

    for (int k0 = 0; k0 < K; k0 += BK) {
        // Load A tile [BM x BK], store transposed As[k][m]
#pragma unroll
        for (int i = tid; i < BM * (BK / 4); i += 256) {
            int r  = i / (BK / 4);
            int kq = i % (BK / 4);
            float4 v = *(const float4*)&A[(size_t)(m0 + r) * K + k0 + 4 * kq];
            As[4 * kq + 0][r] = v.x;
            As[4 * kq + 1][r] = v.y;
            As[4 * kq + 2][r] = v.z;
            As[4 * kq + 3][r] = v.w;
        }
        // Load B tile [BN x BK], store transposed Bs[k][n]
#pragma unroll
        for (int i = tid; i < BN * (BK / 4); i += 256) {
            int r  = i / (BK / 4);
            int kq = i % (BK / 4);
            float4 v = *(const float4*)&B[(size_t)(n0 + r) * K + k0 + 4 * kq];
            Bs[4 * kq + 0][r] = v.x;
            Bs[4 * kq + 1][r] = v.y;
            Bs[4 * kq + 2][r] = v.z;
            Bs[4 * kq + 3][r] = v.w;
        }
        __syncthreads();

#pragma unroll
        for (int kk = 0; kk < BK; kk++) {
            float ar[8], br[8];
            *(float4*)&ar[0] = *(const float4*)&As[kk][ty * 8];
            *(float4*)&ar[4] = *(const float4*)&As[kk][ty * 8 + 4];
            *(float4*)&br[0] = *(const float4*)&Bs[kk][tx * 8];
            *(float4*)&br[4] = *(const float4*)&Bs[kk][tx * 8 + 4];
#pragma unroll
            for (int i = 0; i < 8; i++)
#pragma unroll
                for (int j = 0; j < 8; j++)
                    acc[i][j] += ar[i] * br[j];
        }
        __syncthreads();
    }

#pragma unroll
    for (int i = 0; i < 8; i++) {
#pragma unroll
        for (int j = 0; j < 8; j += 4) {
            float4 v;
            v.x = acc[i][j + 0];
            v.y = acc[i][j + 1];
            v.z = acc[i][j + 2];
            v.w = acc[i][j + 3];
            *(float4*)&C[(size_t)(m0 + ty * 8 + i) * N + n0 + tx * 8 + j] = v;
        }
    }
}

__global__ __launch_bounds__(256)
void qkv_gemm_kernel(const float* __restrict__ x, const float* __restrict__ w_attn)
{
    sgemm_nt_body<128, 128, 16>(x, w_attn, g_qkv, T_SEQ, F_DIM, C_DIM);
}

__global__ __launch_bounds__(256)
void proj_gemm_kernel(const float* __restrict__ w_proj, float* __restrict__ out)
{
    sgemm_nt_body<128, 128, 16>(g_y, w_proj, out, T_SEQ, C_DIM, C_DIM);
}

// ---------------------------------------------------------------------------
// Causal flash attention.
// Grid: (T/128, H). Block: 128 threads; thread t owns query row q0+t.
// q[64], o[64] in registers; K/V chunks of 32 rows in shared (broadcast reads,
// float4 -> 4 FMA per LDS.128). Online softmax.
// ---------------------------------------------------------------------------
__global__ __launch_bounds__(128)
void attn_kernel()
{
    const int q0  = blockIdx.x * 128;
    const int h   = blockIdx.y;
    const int tid = threadIdx.x;
    const int qr  = q0 + tid;

    const size_t qoff = (size_t)h * D_HEAD;
    const size_t koff = (size_t)C_DIM + (size_t)h * D_HEAD;
    const size_t voff = (size_t)2 * C_DIM + (size_t)h * D_HEAD;

    __shared__ float Ks[32][64];
    __shared__ float Vs[32][64];

    float q[64], o[64];
#pragma unroll
    for (int d4 = 0; d4 < 16; d4++) {
        float4 v = *(const float4*)&g_qkv[(size_t)qr * F_DIM + qoff + 4 * d4];
        q[4 * d4 + 0] = v.x;
        q[4 * d4 + 1] = v.y;
        q[4 * d4 + 2] = v.z;
        q[4 * d4 + 3] = v.w;
    }
#pragma unroll
    for (int d = 0; d < 64; d++) o[d] = 0.f;

    float m = -1e30f;
    float l = 0.f;
    const float scale = 0.125f;  // 1/sqrt(64)

    const int nChunks = q0 / 32 + 4;  // covers keys up to q0+127 inclusive
    for (int j = 0; j < nChunks; j++) {
        const int k0 = j * 32;

        // cooperative load of K,V chunk [32 x 64]
#pragma unroll
        for (int i = tid; i < 32 * 64; i += 128) {
            int r = i >> 6;
            int d = i & 63;
            Ks[r][d] = g_qkv[(size_t)(k0 + r) * F_DIM + koff + d];
            Vs[r][d] = g_qkv[(size_t)(k0 + r) * F_DIM + voff + d];
        }
        __syncthreads();

        float s[32];
#pragma unroll
        for (int n = 0; n < 32; n++) {
            const float4* k4 = (const float4*)&Ks[n][0];
            float dot = 0.f;
#pragma unroll
            for (int d4 = 0; d4 < 16; d4++) {
                float4 kv = k4[d4];
                dot += q[4 * d4 + 0] * kv.x;
                dot += q[4 * d4 + 1] * kv.y;
                dot += q[4 * d4 + 2] * kv.z;
                dot += q[4 * d4 + 3] * kv.w;
            }
            s[n] = (k0 + n <= qr) ? dot * scale : -1e30f;
        }

        float mnew = m;
#pragma unroll
        for (int n = 0; n < 32; n++) mnew = fmaxf(mnew, s[n]);

        float alpha = __expf(m - mnew);
        m = mnew;
        l *= alpha;
#pragma unroll
        for (int d = 0; d < 64; d++) o[d] *= alpha;

#pragma unroll
        for (int n = 0; n < 32; n++) {
            float p = __expf(s[n] - mnew);
            l += p;
            const float4* v4 = (const float4*)&Vs[n][0];
#pragma unroll
            for (int d4 = 0; d4 < 16; d4++) {
                float4 vv = v4[d4];
                o[4 * d4 + 0] += p * vv.x;
                o[4 * d4 + 1] += p * vv.y;
                o[4 * d4 + 2] += p * vv.z;
                o[4 * d4 + 3] += p * vv.w;
            }
        }
        __syncthreads();
    }

    const float inv = 1.f / l;
#pragma unroll
    for (int d4 = 0; d4 < 16; d4++) {
        float4 v;
        v.x = o[4 * d4 + 0] * inv;
        v.y = o[4 * d4 + 1] * inv;
        v.z = o[4 * d4 + 2] * inv;
        v.w = o[4 * d4 + 3] * inv;
        *(float4*)&g_y[(size_t)qr * C_DIM + (size_t)h * D_HEAD + 4 * d4] = v;
    }
}

// ---------------------------------------------------------------------------
extern "C" void kernel_launch(void* const* d_in, const int* in_sizes, int n_in,
                              void* d_out, int out_size)
{
    const float* x      = (const float*)d_in[0];  // [1, 4096, 1024]
    const float* w_attn = (const float*)d_in[1];  // [3072, 1024]
    const float* w_proj = (const float*)d_in[2];  // [1024, 1024]
    float* out = (float*)d_out;                   // [1, 4096, 1024]

    (void)in_sizes; (void)n_in; (void)out_size;

    // 1) qkv = x @ w_attn^T  -> g_qkv [4096, 3072]
    qkv_gemm_kernel<<<dim3(F_DIM / 128, T_SEQ / 128), 256>>>(x, w_attn);

    // 2) causal flash attention -> g_y [4096, 1024]
    attn_kernel<<<dim3(T_SEQ / 128, H_NUM), 128>>>();

    // 3) out = y @ w_proj^T
    proj_gemm_kernel<<<dim3(C_DIM / 128, T_SEQ / 128), 256>>>(w_proj, out);
}

// round 3
// speedup vs baseline: 6.0950x; 6.0950x over previous
#include <cuda_runtime.h>
#include <cuda_bf16.h>
#include <cstdint>

#define T_SEQ  4096
#define C_DIM  1024
#define H_NUM  16
#define D_HEAD 64
#define F_DIM  3072

// ---------------------------------------------------------------------------
// Device globals (no allocations allowed)
// ---------------------------------------------------------------------------
__device__ __nv_bfloat16 g_xh[T_SEQ * C_DIM],  g_xl[T_SEQ * C_DIM];
__device__ __nv_bfloat16 g_wah[F_DIM * C_DIM], g_wal[F_DIM * C_DIM];
__device__ __nv_bfloat16 g_wph[C_DIM * C_DIM], g_wpl[C_DIM * C_DIM];
__device__ __nv_bfloat16 g_qkvh[(size_t)T_SEQ * F_DIM], g_qkvl[(size_t)T_SEQ * F_DIM];
__device__ __nv_bfloat16 g_yh[T_SEQ * C_DIM],  g_yl[T_SEQ * C_DIM];

// ---------------------------------------------------------------------------
// Helpers
// ---------------------------------------------------------------------------
__device__ __forceinline__ uint32_t s2u(const void* p) {
    uint32_t a;
    asm("{ .reg .u64 t; cvta.to.shared.u64 t, %1; cvt.u32.u64 %0, t; }"
        : "=r"(a) : "l"(p));
    return a;
}
#define SW128(o) ((uint32_t)(o) ^ ((((uint32_t)(o)) >> 3) & 0x70))

__device__ __forceinline__ void ldsm4(uint32_t* r, uint32_t addr) {
    asm volatile("ldmatrix.sync.aligned.m8n8.x4.shared.b16 {%0,%1,%2,%3}, [%4];"
                 : "=r"(r[0]), "=r"(r[1]), "=r"(r[2]), "=r"(r[3]) : "r"(addr));
}
__device__ __forceinline__ void ldsm4t(uint32_t* r, uint32_t addr) {
    asm volatile("ldmatrix.sync.aligned.m8n8.x4.trans.shared.b16 {%0,%1,%2,%3}, [%4];"
                 : "=r"(r[0]), "=r"(r[1]), "=r"(r[2]), "=r"(r[3]) : "r"(addr));
}
__device__ __forceinline__ void mma16816(float* c, const uint32_t* a,
                                         uint32_t b0, uint32_t b1) {
    asm volatile("mma.sync.aligned.m16n8k16.row.col.f32.bf16.bf16.f32 "
                 "{%0,%1,%2,%3}, {%4,%5,%6,%7}, {%8,%9}, {%0,%1,%2,%3};"
                 : "+f"(c[0]), "+f"(c[1]), "+f"(c[2]), "+f"(c[3])
                 : "r"(a[0]), "r"(a[1]), "r"(a[2]), "r"(a[3]), "r"(b0), "r"(b1));
}
#define CP16(s, g)  asm volatile("cp.async.cg.shared.global [%0], [%1], 16;" :: "r"(s), "l"(g))
#define CPCOMMIT()  asm volatile("cp.async.commit_group;" ::: "memory")
#define CPWAIT1()   asm volatile("cp.async.wait_group 1;" ::: "memory")
#define CPWAIT0()   asm volatile("cp.async.wait_group 0;" ::: "memory")

__device__ __forceinline__ float bf16rf(float x) {
    return __bfloat162float(__float2bfloat16_rn(x));
}
__device__ __forceinline__ uint32_t packbf(float lo, float hi) {
    __nv_bfloat162 t = __floats2bfloat162_rn(lo, hi);
    return reinterpret_cast<uint32_t&>(t);
}

// ---------------------------------------------------------------------------
// fp32 -> (bf16 hi, bf16 lo) split
// ---------------------------------------------------------------------------
__global__ __launch_bounds__(256)
void cvt_split_kernel(const float* __restrict__ in,
                      __nv_bfloat16* __restrict__ hi,
                      __nv_bfloat16* __restrict__ lo, int n4)
{
    int i = blockIdx.x * 256 + threadIdx.x;
    if (i >= n4) return;
    float4 v = ((const float4*)in)[i];
    float h0 = bf16rf(v.x), h1 = bf16rf(v.y), h2 = bf16rf(v.z), h3 = bf16rf(v.w);
    ((uint32_t*)hi)[2 * i]     = packbf(v.x, v.y);
    ((uint32_t*)hi)[2 * i + 1] = packbf(v.z, v.w);
    ((uint32_t*)lo)[2 * i]     = packbf(v.x - h0, v.y - h1);
    ((uint32_t*)lo)[2 * i + 1] = packbf(v.z - h2, v.w - h3);
}

// ---------------------------------------------------------------------------
// bf16x3 GEMM via mma.sync:  C[M,N] = sum_k A[m,k]*B[n,k], A/B K-major bf16
// hi/lo pre-split.  BM=BN=128, BK=64, 256 threads (8 warps, warp tile 32x64),
// SW128 smem rows of 128B, 2-stage cp.async pipeline.
// SPLIT_OUT: write bf16 hi/lo pair instead of fp32.
// ---------------------------------------------------------------------------
#define GST 65536  // stage size: Ah 16K | Al 16K | Bh 16K | Bl 16K
#define OAH 0
#define OAL 16384
#define OBH 32768
#define OBL 49152
#define GEMM_SMEM (2 * GST + 1024)

template<bool SPLIT_OUT>
__global__ __launch_bounds__(256)
void gemm_kernel(const __nv_bfloat16* __restrict__ Ah,
                 const __nv_bfloat16* __restrict__ Al,
                 const __nv_bfloat16* __restrict__ Bh,
                 const __nv_bfloat16* __restrict__ Bl,
                 float* __restrict__ Cout,
                 __nv_bfloat16* __restrict__ Ch,
                 __nv_bfloat16* __restrict__ Cl,
                 int K, int N)
{
    extern __shared__ char smraw[];
    const uint32_t sb = (s2u(smraw) + 1023u) & ~1023u;
    const int tid  = threadIdx.x;
    const int lane = tid & 31;
    const int w    = tid >> 5;
    const int wm   = w & 3;        // 0..3 along M
    const int wn   = w >> 2;       // 0..1 along N
    const int m0   = blockIdx.y * 128;
    const int n0   = blockIdx.x * 128;

    // ---- async stage loader ----
    auto load_stage = [&](int stage, int kt) {
        const uint32_t s0 = sb + stage * GST;
        const int kk = kt * 64;
#pragma unroll
        for (int it = 0; it < 4; it++) {
            int idx = tid + it * 256;          // 0..1023
            int r = idx >> 3, q = idx & 7;
            uint32_t so = SW128(r * 128 + q * 16);
            CP16(s0 + OAH + so, (const void*)(Ah + (size_t)(m0 + r) * K + kk + q * 8));
        }
#pragma unroll
        for (int it = 0; it < 4; it++) {
            int idx = tid + it * 256;
            int r = idx >> 3, q = idx & 7;
            uint32_t so = SW128(r * 128 + q * 16);
            CP16(s0 + OAL + so, (const void*)(Al + (size_t)(m0 + r) * K + kk + q * 8));
        }
#pragma unroll
        for (int it = 0; it < 4; it++) {
            int idx = tid + it * 256;
            int r = idx >> 3, q = idx & 7;
            uint32_t so = SW128(r * 128 + q * 16);
            CP16(s0 + OBH + so, (const void*)(Bh + (size_t)(n0 + r) * K + kk + q * 8));
        }
#pragma unroll
        for (int it = 0; it < 4; it++) {
            int idx = tid + it * 256;
            int r = idx >> 3, q = idx & 7;
            uint32_t so = SW128(r * 128 + q * 16);
            CP16(s0 + OBL + so, (const void*)(Bl + (size_t)(n0 + r) * K + kk + q * 8));
        }
        CPCOMMIT();
    };

    float c[2][8][4];
#pragma unroll
    for (int mt = 0; mt < 2; mt++)
#pragma unroll
        for (int o = 0; o < 8; o++)
#pragma unroll
            for (int e = 0; e < 4; e++) c[mt][o][e] = 0.f;

    const int nT = K / 64;
    load_stage(0, 0);
    load_stage(1, 1);

    for (int t = 0; t < nT; t++) {
        if (t + 1 < nT) CPWAIT1(); else CPWAIT0();
        __syncthreads();
        const uint32_t s0 = sb + (t & 1) * GST;

#pragma unroll
        for (int ks = 0; ks < 4; ks++) {
            const uint32_t kb = ks * 32 + (lane >> 4) * 16;
            uint32_t ah[2][4], al[2][4];
#pragma unroll
            for (int mt = 0; mt < 2; mt++) {
                uint32_t ro = (wm * 32 + mt * 16 + (lane & 15)) * 128 + kb;
                ldsm4(ah[mt], s0 + OAH + SW128(ro));
                ldsm4(al[mt], s0 + OAL + SW128(ro));
            }
            uint32_t bh[4][4], bl[4][4];
#pragma unroll
            for (int nt = 0; nt < 4; nt++) {
                uint32_t ro = (wn * 64 + nt * 16 + (lane & 15)) * 128 + kb;
                ldsm4(bh[nt], s0 + OBH + SW128(ro));
                ldsm4(bl[nt], s0 + OBL + SW128(ro));
            }
#pragma unroll
            for (int mt = 0; mt < 2; mt++) {
#pragma unroll
                for (int nt = 0; nt < 4; nt++) {
                    mma16816(c[mt][2 * nt],     ah[mt], bh[nt][0], bh[nt][2]);
                    mma16816(c[mt][2 * nt],     ah[mt], bl[nt][0], bl[nt][2]);
                    mma16816(c[mt][2 * nt],     al[mt], bh[nt][0], bh[nt][2]);
                    mma16816(c[mt][2 * nt + 1], ah[mt], bh[nt][1], bh[nt][3]);
                    mma16816(c[mt][2 * nt + 1], ah[mt], bl[nt][1], bl[nt][3]);
                    mma16816(c[mt][2 * nt + 1], al[mt], bh[nt][1], bh[nt][3]);
                }
            }
        }
        __syncthreads();
        if (t + 2 < nT) load_stage(t & 1, t + 2);
    }

    // ---- epilogue ----
    const int rbase = m0 + wm * 32 + (lane >> 2);
    const int cbase = n0 + wn * 64 + (lane & 3) * 2;
#pragma unroll
    for (int mt = 0; mt < 2; mt++) {
#pragma unroll
        for (int o = 0; o < 8; o++) {
            int col = cbase + o * 8;
            int r0 = rbase + mt * 16;
            int r1 = r0 + 8;
            if (SPLIT_OUT) {
                float v0 = c[mt][o][0], v1 = c[mt][o][1];
                float v2 = c[mt][o][2], v3 = c[mt][o][3];
                float h0 = bf16rf(v0), h1 = bf16rf(v1), h2 = bf16rf(v2), h3 = bf16rf(v3);
                *(uint32_t*)&Ch[(size_t)r0 * N + col] = packbf(v0, v1);
                *(uint32_t*)&Cl[(size_t)r0 * N + col] = packbf(v0 - h0, v1 - h1);
                *(uint32_t*)&Ch[(size_t)r1 * N + col] = packbf(v2, v3);
                *(uint32_t*)&Cl[(size_t)r1 * N + col] = packbf(v2 - h2, v3 - h3);
            } else {
                float2 a = make_float2(c[mt][o][0], c[mt][o][1]);
                float2 b = make_float2(c[mt][o][2], c[mt][o][3]);
                *(float2*)&Cout[(size_t)r0 * N + col] = a;
                *(float2*)&Cout[(size_t)r1 * N + col] = b;
            }
        }
    }
}

// ---------------------------------------------------------------------------
// Tensor-core causal flash attention (bf16x3 mma).
// Block: 128 threads (4 warps).  Q tile = 64 rows (warp w: rows w*16..+15),
// KV tile = 64.  S/P fragments fp32; P split in registers for PV.
// Smem: Qh|Ql|Kh|Kl|Vh|Vl, each 64x64 bf16 (8KB), SW128 rows.
// ---------------------------------------------------------------------------
#define AQH 0
#define AQL 8192
#define AKH 16384
#define AKL 24576
#define AVH 32768
#define AVL 40960
#define ATTN_SMEM (49152 + 1024)

__global__ __launch_bounds__(128)
void attn_kernel()
{
    extern __shared__ char smraw[];
    const uint32_t sb = (s2u(smraw) + 1023u) & ~1023u;
    const int qt   = (int)gridDim.x - 1 - (int)blockIdx.x;   // heavy tiles first
    const int h    = blockIdx.y;
    const int q0   = qt * 64;
    const int tid  = threadIdx.x;
    const int w    = tid >> 5;
    const int lane = tid & 31;

    // ---- load Q tile (hi/lo bf16 straight copy) ----
#pragma unroll
    for (int it = 0; it < 4; it++) {
        int idx = tid + it * 128;            // 0..511
        int r = idx >> 3, q = idx & 7;
        size_t go = (size_t)(q0 + r) * F_DIM + h * 64 + q * 8;
        uint32_t so = SW128(r * 128 + q * 16);
        uint4 vh = *(const uint4*)&g_qkvh[go];
        uint4 vl = *(const uint4*)&g_qkvl[go];
        asm volatile("st.shared.v4.b32 [%0],{%1,%2,%3,%4};"
                     :: "r"(sb + AQH + so), "r"(vh.x), "r"(vh.y), "r"(vh.z), "r"(vh.w));
        asm volatile("st.shared.v4.b32 [%0],{%1,%2,%3,%4};"
                     :: "r"(sb + AQL + so), "r"(vl.x), "r"(vl.y), "r"(vl.z), "r"(vl.w));
    }
    __syncthreads();

    // Q fragments (A operand), per k16 step
    uint32_t qh[4][4], ql[4][4];
#pragma unroll
    for (int ks = 0; ks < 4; ks++) {
        uint32_t ro = (w * 16 + (lane & 15)) * 128 + ks * 32 + (lane >> 4) * 16;
        ldsm4(qh[ks], sb + AQH + SW128(ro));
        ldsm4(ql[ks], sb + AQL + SW128(ro));
    }

    float o[8][4];
#pragma unroll
    for (int d = 0; d < 8; d++)
#pragma unroll
        for (int e = 0; e < 4; e++) o[d][e] = 0.f;
    float m0v = -1e30f, m1v = -1e30f, l0 = 0.f, l1 = 0.f;

    const int rA = lane >> 2;          // local row within 16 (also +8)
    const int ntiles = qt + 1;

    for (int j = 0; j < ntiles; j++) {
        const int k0 = j * 64;
        __syncthreads();   // previous iteration's reads of K/V smem done
        // ---- load K/V tile ----
#pragma unroll
        for (int it = 0; it < 4; it++) {
            int idx = tid + it * 128;
            int r = idx >> 3, q = idx & 7;
            size_t gro = (size_t)(k0 + r) * F_DIM + h * 64 + q * 8;
            uint32_t so = SW128(r * 128 + q * 16);
            uint4 a = *(const uint4*)&g_qkvh[C_DIM + gro];
            uint4 b = *(const uint4*)&g_qkvl[C_DIM + gro];
            uint4 cdat = *(const uint4*)&g_qkvh[2 * C_DIM + gro];
            uint4 d4 = *(const uint4*)&g_qkvl[2 * C_DIM + gro];
            asm volatile("st.shared.v4.b32 [%0],{%1,%2,%3,%4};"
                         :: "r"(sb + AKH + so), "r"(a.x), "r"(a.y), "r"(a.z), "r"(a.w));
            asm volatile("st.shared.v4.b32 [%0],{%1,%2,%3,%4};"
                         :: "r"(sb + AKL + so), "r"(b.x), "r"(b.y), "r"(b.z), "r"(b.w));
            asm volatile("st.shared.v4.b32 [%0],{%1,%2,%3,%4};"
                         :: "r"(sb + AVH + so), "r"(cdat.x), "r"(cdat.y), "r"(cdat.z), "r"(cdat.w));
            asm volatile("st.shared.v4.b32 [%0],{%1,%2,%3,%4};"
                         :: "r"(sb + AVL + so), "r"(d4.x), "r"(d4.y), "r"(d4.z), "r"(d4.w));
        }
        __syncthreads();

        // ---- S = Q K^T (bf16x3) ----
        float s[8][4];
#pragma unroll
        for (int ot = 0; ot < 8; ot++)
#pragma unroll
            for (int e = 0; e < 4; e++) s[ot][e] = 0.f;
#pragma unroll
        for (int ks = 0; ks < 4; ks++) {
            uint32_t kh[4][4], kl[4][4];
#pragma unroll
            for (int nt = 0; nt < 4; nt++) {
                uint32_t ro = (nt * 16 + (lane & 15)) * 128 + ks * 32 + (lane >> 4) * 16;
                ldsm4(kh[nt], sb + AKH + SW128(ro));
                ldsm4(kl[nt], sb + AKL + SW128(ro));
            }
#pragma unroll
            for (int nt = 0; nt < 4; nt++) {
                mma16816(s[2 * nt],     qh[ks], kh[nt][0], kh[nt][2]);
                mma16816(s[2 * nt],     qh[ks], kl[nt][0], kl[nt][2]);
                mma16816(s[2 * nt],     ql[ks], kh[nt][0], kh[nt][2]);
                mma16816(s[2 * nt + 1], qh[ks], kh[nt][1], kh[nt][3]);
                mma16816(s[2 * nt + 1], qh[ks], kl[nt][1], kl[nt][3]);
                mma16816(s[2 * nt + 1], ql[ks], kh[nt][1], kh[nt][3]);
            }
        }

        // ---- scale + causal mask (diagonal tile only) ----
        const bool diag = (k0 == q0);
#pragma unroll
        for (int ot = 0; ot < 8; ot++)
#pragma unroll
            for (int e = 0; e < 4; e++) {
                float v = s[ot][e] * 0.125f;
                if (diag) {
                    int n = ot * 8 + (lane & 3) * 2 + (e & 1);
                    int r = w * 16 + rA + ((e >= 2) ? 8 : 0);
                    if (n > r) v = -1e30f;
                }
                s[ot][e] = v;
            }

        // ---- online softmax ----
        float mx0 = -1e30f, mx1 = -1e30f;
#pragma unroll
        for (int ot = 0; ot < 8; ot++) {
            mx0 = fmaxf(mx0, fmaxf(s[ot][0], s[ot][1]));
            mx1 = fmaxf(mx1, fmaxf(s[ot][2], s[ot][3]));
        }
        mx0 = fmaxf(mx0, __shfl_xor_sync(0xffffffff, mx0, 1));
        mx0 = fmaxf(mx0, __shfl_xor_sync(0xffffffff, mx0, 2));
        mx1 = fmaxf(mx1, __shfl_xor_sync(0xffffffff, mx1, 1));
        mx1 = fmaxf(mx1, __shfl_xor_sync(0xffffffff, mx1, 2));

        float mn0 = fmaxf(m0v, mx0), mn1 = fmaxf(m1v, mx1);
        float a0 = __expf(m0v - mn0), a1 = __expf(m1v - mn1);
        m0v = mn0; m1v = mn1;
        l0 *= a0;  l1 *= a1;
#pragma unroll
        for (int d = 0; d < 8; d++) {
            o[d][0] *= a0; o[d][1] *= a0;
            o[d][2] *= a1; o[d][3] *= a1;
        }
#pragma unroll
        for (int ot = 0; ot < 8; ot++) {
            float p0 = __expf(s[ot][0] - mn0);
            float p1 = __expf(s[ot][1] - mn0);
            float p2 = __expf(s[ot][2] - mn1);
            float p3 = __expf(s[ot][3] - mn1);
            l0 += p0 + p1; l1 += p2 + p3;
            s[ot][0] = p0; s[ot][1] = p1; s[ot][2] = p2; s[ot][3] = p3;
        }

        // ---- O += P V (bf16x3, P split in regs, V via ldmatrix.trans) ----
#pragma unroll
        for (int kt = 0; kt < 4; kt++) {
            float p00 = s[2 * kt][0],     p01 = s[2 * kt][1];
            float p10 = s[2 * kt][2],     p11 = s[2 * kt][3];
            float r00 = s[2 * kt + 1][0], r01 = s[2 * kt + 1][1];
            float r10 = s[2 * kt + 1][2], r11 = s[2 * kt + 1][3];
            float h00 = bf16rf(p00), h01 = bf16rf(p01), h10 = bf16rf(p10), h11 = bf16rf(p11);
            float g00 = bf16rf(r00), g01 = bf16rf(r01), g10 = bf16rf(r10), g11 = bf16rf(r11);
            uint32_t aph[4] = { packbf(p00, p01), packbf(p10, p11),
                                packbf(r00, r01), packbf(r10, r11) };
            uint32_t apl[4] = { packbf(p00 - h00, p01 - h01), packbf(p10 - h10, p11 - h11),
                                packbf(r00 - g00, r01 - g01), packbf(r10 - g10, r11 - g11) };
#pragma unroll
            for (int dt = 0; dt < 4; dt++) {
                uint32_t vh[4], vl[4];
                uint32_t ro = (kt * 16 + (lane & 15)) * 128 + dt * 32 + (lane >> 4) * 16;
                ldsm4t(vh, sb + AVH + SW128(ro));
                ldsm4t(vl, sb + AVL + SW128(ro));
                mma16816(o[2 * dt],     aph, vh[0], vh[1]);
                mma16816(o[2 * dt],     aph, vl[0], vl[1]);
                mma16816(o[2 * dt],     apl, vh[0], vh[1]);
                mma16816(o[2 * dt + 1], aph, vh[2], vh[3]);
                mma16816(o[2 * dt + 1], aph, vl[2], vl[3]);
                mma16816(o[2 * dt + 1], apl, vh[2], vh[3]);
            }
        }
    }

    // ---- finalize ----
    l0 += __shfl_xor_sync(0xffffffff, l0, 1);
    l0 += __shfl_xor_sync(0xffffffff, l0, 2);
    l1 += __shfl_xor_sync(0xffffffff, l1, 1);
    l1 += __shfl_xor_sync(0xffffffff, l1, 2);
    const float i0 = 1.f / l0, i1 = 1.f / l1;

    const int row0 = q0 + w * 16 + rA;
    const int cb   = h * 64 + (lane & 3) * 2;
#pragma unroll
    for (int d = 0; d < 8; d++) {
        int col = cb + d * 8;
        float v0 = o[d][0] * i0, v1 = o[d][1] * i0;
        float v2 = o[d][2] * i1, v3 = o[d][3] * i1;
        float h0 = bf16rf(v0), h1 = bf16rf(v1), h2 = bf16rf(v2), h3 = bf16rf(v3);
        *(uint32_t*)&g_yh[(size_t)row0 * C_DIM + col]       = packbf(v0, v1);
        *(uint32_t*)&g_yl[(size_t)row0 * C_DIM + col]       = packbf(v0 - h0, v1 - h1);
        *(uint32_t*)&g_yh[(size_t)(row0 + 8) * C_DIM + col] = packbf(v2, v3);
        *(uint32_t*)&g_yl[(size_t)(row0 + 8) * C_DIM + col] = packbf(v2 - h2, v3 - h3);
    }
}

// ---------------------------------------------------------------------------
extern "C" void kernel_launch(void* const* d_in, const int* in_sizes, int n_in,
                              void* d_out, int out_size)
{
    const float* x      = (const float*)d_in[0];
    const float* w_attn = (const float*)d_in[1];
    const float* w_proj = (const float*)d_in[2];
    float* out = (float*)d_out;
    (void)in_sizes; (void)n_in; (void)out_size;

    static bool attr_done = false;
    cudaFuncSetAttribute(gemm_kernel<true>,
                         cudaFuncAttributeMaxDynamicSharedMemorySize, GEMM_SMEM);
    cudaFuncSetAttribute(gemm_kernel<false>,
                         cudaFuncAttributeMaxDynamicSharedMemorySize, GEMM_SMEM);
    cudaFuncSetAttribute(attn_kernel,
                         cudaFuncAttributeMaxDynamicSharedMemorySize, ATTN_SMEM);
    (void)attr_done;

    void *p_xh, *p_xl, *p_wah, *p_wal, *p_wph, *p_wpl, *p_qh, *p_ql, *p_yh, *p_yl;
    cudaGetSymbolAddress(&p_xh, g_xh);   cudaGetSymbolAddress(&p_xl, g_xl);
    cudaGetSymbolAddress(&p_wah, g_wah); cudaGetSymbolAddress(&p_wal, g_wal);
    cudaGetSymbolAddress(&p_wph, g_wph); cudaGetSymbolAddress(&p_wpl, g_wpl);
    cudaGetSymbolAddress(&p_qh, g_qkvh); cudaGetSymbolAddress(&p_ql, g_qkvl);
    cudaGetSymbolAddress(&p_yh, g_yh);   cudaGetSymbolAddress(&p_yl, g_yl);

    // 1) split inputs
    cvt_split_kernel<<<T_SEQ * C_DIM / 4 / 256, 256>>>(
        x, (__nv_bfloat16*)p_xh, (__nv_bfloat16*)p_xl, T_SEQ * C_DIM / 4);
    cvt_split_kernel<<<F_DIM * C_DIM / 4 / 256, 256>>>(
        w_attn, (__nv_bfloat16*)p_wah, (__nv_bfloat16*)p_wal, F_DIM * C_DIM / 4);
    cvt_split_kernel<<<C_DIM * C_DIM / 4 / 256, 256>>>(
        w_proj, (__nv_bfloat16*)p_wph, (__nv_bfloat16*)p_wpl, C_DIM * C_DIM / 4);

    // 2) qkv = x @ w_attn^T  -> split bf16 output
    gemm_kernel<true><<<dim3(F_DIM / 128, T_SEQ / 128), 256, GEMM_SMEM>>>(
        (const __nv_bfloat16*)p_xh, (const __nv_bfloat16*)p_xl,
        (const __nv_bfloat16*)p_wah, (const __nv_bfloat16*)p_wal,
        nullptr, (__nv_bfloat16*)p_qh, (__nv_bfloat16*)p_ql, C_DIM, F_DIM);

    // 3) tensor-core causal attention -> split bf16 y
    attn_kernel<<<dim3(T_SEQ / 64, H_NUM), 128, ATTN_SMEM>>>();

    // 4) out = y @ w_proj^T  (fp32 output)
    gemm_kernel<false><<<dim3(C_DIM / 128, T_SEQ / 128), 256, GEMM_SMEM>>>(
        (const __nv_bfloat16*)p_yh, (const __nv_bfloat16*)p_yl,
        (const __nv_bfloat16*)p_wph, (const __nv_bfloat16*)p_wpl,
        out, nullptr, nullptr, C_DIM, C_DIM);
}

// round 9
// speedup vs baseline: 6.7891x; 1.1139x over previous
#include <cuda_runtime.h>
#include <cuda_bf16.h>
#include <cstdint>

#define T_SEQ  4096
#define C_DIM  1024
#define H_NUM  16
#define D_HEAD 64
#define F_DIM  3072

// ---------------------------------------------------------------------------
// Device globals (no allocations allowed)
// ---------------------------------------------------------------------------
__device__ __nv_bfloat16 g_xh[T_SEQ * C_DIM],  g_xl[T_SEQ * C_DIM];
__device__ __nv_bfloat16 g_wah[F_DIM * C_DIM], g_wal[F_DIM * C_DIM];
__device__ __nv_bfloat16 g_wph[C_DIM * C_DIM], g_wpl[C_DIM * C_DIM];
__device__ __nv_bfloat16 g_qkvh[(size_t)T_SEQ * F_DIM], g_qkvl[(size_t)T_SEQ * F_DIM];
__device__ __nv_bfloat16 g_yh[T_SEQ * C_DIM],  g_yl[T_SEQ * C_DIM];

// ---------------------------------------------------------------------------
// Helpers
// ---------------------------------------------------------------------------
__device__ __forceinline__ uint32_t s2u(const void* p) {
    uint32_t a;
    asm("{ .reg .u64 t; cvta.to.shared.u64 t, %1; cvt.u32.u64 %0, t; }"
        : "=r"(a) : "l"(p));
    return a;
}
#define SW128(o) ((uint32_t)(o) ^ ((((uint32_t)(o)) >> 3) & 0x70))

__device__ __forceinline__ void ldsm4(uint32_t* r, uint32_t addr) {
    asm volatile("ldmatrix.sync.aligned.m8n8.x4.shared.b16 {%0,%1,%2,%3}, [%4];"
                 : "=r"(r[0]), "=r"(r[1]), "=r"(r[2]), "=r"(r[3]) : "r"(addr));
}
__device__ __forceinline__ void ldsm4t(uint32_t* r, uint32_t addr) {
    asm volatile("ldmatrix.sync.aligned.m8n8.x4.trans.shared.b16 {%0,%1,%2,%3}, [%4];"
                 : "=r"(r[0]), "=r"(r[1]), "=r"(r[2]), "=r"(r[3]) : "r"(addr));
}
__device__ __forceinline__ void mma16816(float* c, const uint32_t* a,
                                         uint32_t b0, uint32_t b1) {
    asm volatile("mma.sync.aligned.m16n8k16.row.col.f32.bf16.bf16.f32 "
                 "{%0,%1,%2,%3}, {%4,%5,%6,%7}, {%8,%9}, {%0,%1,%2,%3};"
                 : "+f"(c[0]), "+f"(c[1]), "+f"(c[2]), "+f"(c[3])
                 : "r"(a[0]), "r"(a[1]), "r"(a[2]), "r"(a[3]), "r"(b0), "r"(b1));
}
#define CP16(s, g)  asm volatile("cp.async.cg.shared.global [%0], [%1], 16;" :: "r"(s), "l"(g))
#define CPCOMMIT()  asm volatile("cp.async.commit_group;" ::: "memory")
#define CPWAIT1()   asm volatile("cp.async.wait_group 1;" ::: "memory")
#define CPWAIT0()   asm volatile("cp.async.wait_group 0;" ::: "memory")

__device__ __forceinline__ float bf16rf(float x) {
    return __bfloat162float(__float2bfloat16_rn(x));
}
__device__ __forceinline__ uint32_t packbf(float lo, float hi) {
    __nv_bfloat162 t = __floats2bfloat162_rn(lo, hi);
    return reinterpret_cast<uint32_t&>(t);
}

// ---------------------------------------------------------------------------
// fp32 -> (bf16 hi, bf16 lo) split
// ---------------------------------------------------------------------------
__global__ __launch_bounds__(256)
void cvt_split_kernel(const float* __restrict__ in,
                      __nv_bfloat16* __restrict__ hi,
                      __nv_bfloat16* __restrict__ lo, int n4)
{
    int i = blockIdx.x * 256 + threadIdx.x;
    if (i >= n4) return;
    float4 v = ((const float4*)in)[i];
    float h0 = bf16rf(v.x), h1 = bf16rf(v.y), h2 = bf16rf(v.z), h3 = bf16rf(v.w);
    ((uint32_t*)hi)[2 * i]     = packbf(v.x, v.y);
    ((uint32_t*)hi)[2 * i + 1] = packbf(v.z, v.w);
    ((uint32_t*)lo)[2 * i]     = packbf(v.x - h0, v.y - h1);
    ((uint32_t*)lo)[2 * i + 1] = packbf(v.z - h2, v.w - h3);
}

// ---------------------------------------------------------------------------
// bf16x3 GEMM:  C[M,N] = sum_k A[m,k]*B[n,k].  BM=128, BN=256, BK=64.
// 512 threads (16 warps: 4 along M x 4 along N, warp tile 32x64).
// 2-stage cp.async pipeline.
// ---------------------------------------------------------------------------
#define OAH 0
#define OAL 16384
#define OBH 32768        // B: 256 rows * 128B = 32KB
#define OBL 65536
#define GST 98304        // 96KB stage
#define GEMM_SMEM (2 * GST + 1024)

template<bool SPLIT_OUT>
__global__ __launch_bounds__(512, 1)
void gemm_kernel(const __nv_bfloat16* __restrict__ Ah,
                 const __nv_bfloat16* __restrict__ Al,
                 const __nv_bfloat16* __restrict__ Bh,
                 const __nv_bfloat16* __restrict__ Bl,
                 float* __restrict__ Cout,
                 __nv_bfloat16* __restrict__ Ch,
                 __nv_bfloat16* __restrict__ Cl,
                 int K, int N)
{
    extern __shared__ char smraw[];
    const uint32_t sb = (s2u(smraw) + 1023u) & ~1023u;
    const int tid  = threadIdx.x;
    const int lane = tid & 31;
    const int w    = tid >> 5;
    const int wm   = w & 3;        // 0..3 along M (32 rows each)
    const int wn   = w >> 2;       // 0..3 along N (64 cols each)
    const int m0   = blockIdx.y * 128;
    const int n0   = blockIdx.x * 256;

    auto load_stage = [&](int stage, int kt) {
        const uint32_t s0 = sb + stage * GST;
        const int kk = kt * 64;
#pragma unroll
        for (int it = 0; it < 2; it++) {
            int idx = tid + it * 512;           // 0..1023
            int r = idx >> 3, q = idx & 7;
            uint32_t so = SW128(r * 128 + q * 16);
            CP16(s0 + OAH + so, (const void*)(Ah + (size_t)(m0 + r) * K + kk + q * 8));
            CP16(s0 + OAL + so, (const void*)(Al + (size_t)(m0 + r) * K + kk + q * 8));
        }
#pragma unroll
        for (int it = 0; it < 4; it++) {
            int idx = tid + it * 512;           // 0..2047
            int r = idx >> 3, q = idx & 7;
            uint32_t so = SW128(r * 128 + q * 16);
            CP16(s0 + OBH + so, (const void*)(Bh + (size_t)(n0 + r) * K + kk + q * 8));
            CP16(s0 + OBL + so, (const void*)(Bl + (size_t)(n0 + r) * K + kk + q * 8));
        }
        CPCOMMIT();
    };

    float c[2][8][4];
#pragma unroll
    for (int mt = 0; mt < 2; mt++)
#pragma unroll
        for (int o = 0; o < 8; o++)
#pragma unroll
            for (int e = 0; e < 4; e++) c[mt][o][e] = 0.f;

    const int nT = K / 64;
    load_stage(0, 0);
    load_stage(1, 1);

    for (int t = 0; t < nT; t++) {
        if (t + 1 < nT) CPWAIT1(); else CPWAIT0();
        __syncthreads();
        const uint32_t s0 = sb + (t & 1) * GST;

#pragma unroll
        for (int ks = 0; ks < 4; ks++) {
            const uint32_t kb = ks * 32 + (lane >> 4) * 16;
            uint32_t ah[2][4], al[2][4];
#pragma unroll
            for (int mt = 0; mt < 2; mt++) {
                uint32_t ro = (wm * 32 + mt * 16 + (lane & 15)) * 128 + kb;
                ldsm4(ah[mt], s0 + OAH + SW128(ro));
                ldsm4(al[mt], s0 + OAL + SW128(ro));
            }
            uint32_t bh[4][4], bl[4][4];
#pragma unroll
            for (int nt = 0; nt < 4; nt++) {
                uint32_t ro = (wn * 64 + nt * 16 + (lane & 15)) * 128 + kb;
                ldsm4(bh[nt], s0 + OBH + SW128(ro));
                ldsm4(bl[nt], s0 + OBL + SW128(ro));
            }
            // term 1: Ah*Bh  (16 independent mmas)
#pragma unroll
            for (int mt = 0; mt < 2; mt++)
#pragma unroll
                for (int nt = 0; nt < 4; nt++) {
                    mma16816(c[mt][2 * nt],     ah[mt], bh[nt][0], bh[nt][2]);
                    mma16816(c[mt][2 * nt + 1], ah[mt], bh[nt][1], bh[nt][3]);
                }
            // term 2: Ah*Bl
#pragma unroll
            for (int mt = 0; mt < 2; mt++)
#pragma unroll
                for (int nt = 0; nt < 4; nt++) {
                    mma16816(c[mt][2 * nt],     ah[mt], bl[nt][0], bl[nt][2]);
                    mma16816(c[mt][2 * nt + 1], ah[mt], bl[nt][1], bl[nt][3]);
                }
            // term 3: Al*Bh
#pragma unroll
            for (int mt = 0; mt < 2; mt++)
#pragma unroll
                for (int nt = 0; nt < 4; nt++) {
                    mma16816(c[mt][2 * nt],     al[mt], bh[nt][0], bh[nt][2]);
                    mma16816(c[mt][2 * nt + 1], al[mt], bh[nt][1], bh[nt][3]);
                }
        }
        __syncthreads();
        if (t + 2 < nT) load_stage(t & 1, t + 2);
    }

    // ---- epilogue ----
    const int rbase = m0 + wm * 32 + (lane >> 2);
    const int cbase = n0 + wn * 64 + (lane & 3) * 2;
#pragma unroll
    for (int mt = 0; mt < 2; mt++) {
#pragma unroll
        for (int o = 0; o < 8; o++) {
            int col = cbase + o * 8;
            int r0 = rbase + mt * 16;
            int r1 = r0 + 8;
            if (SPLIT_OUT) {
                float v0 = c[mt][o][0], v1 = c[mt][o][1];
                float v2 = c[mt][o][2], v3 = c[mt][o][3];
                float h0 = bf16rf(v0), h1 = bf16rf(v1), h2 = bf16rf(v2), h3 = bf16rf(v3);
                *(uint32_t*)&Ch[(size_t)r0 * N + col] = packbf(v0, v1);
                *(uint32_t*)&Cl[(size_t)r0 * N + col] = packbf(v0 - h0, v1 - h1);
                *(uint32_t*)&Ch[(size_t)r1 * N + col] = packbf(v2, v3);
                *(uint32_t*)&Cl[(size_t)r1 * N + col] = packbf(v2 - h2, v3 - h3);
            } else {
                *(float2*)&Cout[(size_t)r0 * N + col] = make_float2(c[mt][o][0], c[mt][o][1]);
                *(float2*)&Cout[(size_t)r1 * N + col] = make_float2(c[mt][o][2], c[mt][o][3]);
            }
        }
    }
}

// ---------------------------------------------------------------------------
// Tensor-core causal flash attention, bf16x3, cp.async 3-buffer KV pipeline.
// Block: 256 threads (8 warps), Q tile = 128 rows (warp w: rows w*16..+15),
// KV tile = 64 keys.
// Smem: Qh(16K)|Ql(16K) | 3 x [Kh 8K|Kl 8K|Vh 8K|Vl 8K]
// ---------------------------------------------------------------------------
#define AQH 0
#define AQL 16384
#define AKV 32768
#define KVB 32768                       // per-buffer size
#define ATTN_SMEM (AKV + 3 * KVB + 1024)

__global__ __launch_bounds__(256, 1)
void attn_kernel()
{
    extern __shared__ char smraw[];
    const uint32_t sb = (s2u(smraw) + 1023u) & ~1023u;
    const int qt   = (int)gridDim.x - 1 - (int)blockIdx.x;   // heavy tiles first
    const int h    = blockIdx.y;
    const int q0   = qt * 128;
    const int tid  = threadIdx.x;
    const int w    = tid >> 5;
    const int lane = tid & 31;
    const int ntiles = 2 * qt + 2;

    auto load_kv = [&](int buf, int j) {
        const int k0 = j * 64;
        const uint32_t b0 = sb + AKV + buf * KVB;
#pragma unroll
        for (int it = 0; it < 8; it++) {
            int idx = tid + it * 256;       // 0..2047
            int arr = idx >> 9;             // 0..3 : Kh,Kl,Vh,Vl
            int rem = idx & 511;
            int r = rem >> 3, q = rem & 7;
            uint32_t so = SW128(r * 128 + q * 16) + arr * 8192;
            size_t go = (size_t)(k0 + r) * F_DIM + h * 64 + q * 8;
            const __nv_bfloat16* src;
            if (arr == 0)      src = g_qkvh + C_DIM + go;
            else if (arr == 1) src = g_qkvl + C_DIM + go;
            else if (arr == 2) src = g_qkvh + 2 * C_DIM + go;
            else               src = g_qkvl + 2 * C_DIM + go;
            CP16(b0 + so, (const void*)src);
        }
        CPCOMMIT();
    };

    // prefetch KV tile 0 first (overlaps with Q staging)
    load_kv(0, 0);

    // ---- stage Q tile (hi/lo) ----
#pragma unroll
    for (int it = 0; it < 4; it++) {
        int idx = tid + it * 256;            // 0..1023
        int r = idx >> 3, q = idx & 7;
        size_t go = (size_t)(q0 + r) * F_DIM + h * 64 + q * 8;
        uint32_t so = SW128(r * 128 + q * 16);
        uint4 vh = *(const uint4*)&g_qkvh[go];
        uint4 vl = *(const uint4*)&g_qkvl[go];
        asm volatile("st.shared.v4.b32 [%0],{%1,%2,%3,%4};"
                     :: "r"(sb + AQH + so), "r"(vh.x), "r"(vh.y), "r"(vh.z), "r"(vh.w));
        asm volatile("st.shared.v4.b32 [%0],{%1,%2,%3,%4};"
                     :: "r"(sb + AQL + so), "r"(vl.x), "r"(vl.y), "r"(vl.z), "r"(vl.w));
    }
    __syncthreads();

    // Q fragments (A operand), rows w*16..w*16+15, per k16 step
    uint32_t qh[4][4], ql[4][4];
#pragma unroll
    for (int ks = 0; ks < 4; ks++) {
        uint32_t ro = (w * 16 + (lane & 15)) * 128 + ks * 32 + (lane >> 4) * 16;
        ldsm4(qh[ks], sb + AQH + SW128(ro));
        ldsm4(ql[ks], sb + AQL + SW128(ro));
    }

    float o[8][4];
#pragma unroll
    for (int d = 0; d < 8; d++)
#pragma unroll
        for (int e = 0; e < 4; e++) o[d][e] = 0.f;
    float m0v = -1e30f, m1v = -1e30f, l0 = 0.f, l1 = 0.f;

    const int rA = lane >> 2;
    const int wrow_min = q0 + w * 16;       // this warp's first query row
    const int wrow_max = wrow_min + 15;

    for (int j = 0; j < ntiles; j++) {
        const int k0 = j * 64;
        if (j + 1 < ntiles) load_kv((j + 1) % 3, j + 1);
        if (j + 1 < ntiles) CPWAIT1(); else CPWAIT0();
        __syncthreads();

        if (k0 > wrow_max) continue;        // fully masked for this warp

        const uint32_t kvb = sb + AKV + (j % 3) * KVB;

        // ---- S = Q K^T (bf16x3) ----
        float s[8][4];
#pragma unroll
        for (int ot = 0; ot < 8; ot++)
#pragma unroll
            for (int e = 0; e < 4; e++) s[ot][e] = 0.f;
#pragma unroll
        for (int ks = 0; ks < 4; ks++) {
            uint32_t kh[4][4], kl[4][4];
#pragma unroll
            for (int nt = 0; nt < 4; nt++) {
                uint32_t ro = (nt * 16 + (lane & 15)) * 128 + ks * 32 + (lane >> 4) * 16;
                ldsm4(kh[nt], kvb + SW128(ro));
                ldsm4(kl[nt], kvb + 8192 + SW128(ro));
            }
#pragma unroll
            for (int nt = 0; nt < 4; nt++) {
                mma16816(s[2 * nt],     qh[ks], kh[nt][0], kh[nt][2]);
                mma16816(s[2 * nt + 1], qh[ks], kh[nt][1], kh[nt][3]);
            }
#pragma unroll
            for (int nt = 0; nt < 4; nt++) {
                mma16816(s[2 * nt],     qh[ks], kl[nt][0], kl[nt][2]);
                mma16816(s[2 * nt + 1], qh[ks], kl[nt][1], kl[nt][3]);
            }
#pragma unroll
            for (int nt = 0; nt < 4; nt++) {
                mma16816(s[2 * nt],     ql[ks], kh[nt][0], kh[nt][2]);
                mma16816(s[2 * nt + 1], ql[ks], kh[nt][1], kh[nt][3]);
            }
        }

        // ---- scale + causal mask ----
        const bool need_mask = (k0 + 63 > wrow_min);
#pragma unroll
        for (int ot = 0; ot < 8; ot++)
#pragma unroll
            for (int e = 0; e < 4; e++) {
                float v = s[ot][e] * 0.125f;
                if (need_mask) {
                    int n = k0 + ot * 8 + (lane & 3) * 2 + (e & 1);
                    int r = wrow_min + rA + ((e >= 2) ? 8 : 0);
                    if (n > r) v = -1e30f;
                }
                s[ot][e] = v;
            }

        // ---- online softmax ----
        float mx0 = -1e30f, mx1 = -1e30f;
#pragma unroll
        for (int ot = 0; ot < 8; ot++) {
            mx0 = fmaxf(mx0, fmaxf(s[ot][0], s[ot][1]));
            mx1 = fmaxf(mx1, fmaxf(s[ot][2], s[ot][3]));
        }
        mx0 = fmaxf(mx0, __shfl_xor_sync(0xffffffff, mx0, 1));
        mx0 = fmaxf(mx0, __shfl_xor_sync(0xffffffff, mx0, 2));
        mx1 = fmaxf(mx1, __shfl_xor_sync(0xffffffff, mx1, 1));
        mx1 = fmaxf(mx1, __shfl_xor_sync(0xffffffff, mx1, 2));

        float mn0 = fmaxf(m0v, mx0), mn1 = fmaxf(m1v, mx1);
        float a0 = __expf(m0v - mn0), a1 = __expf(m1v - mn1);
        m0v = mn0; m1v = mn1;
        l0 *= a0;  l1 *= a1;
#pragma unroll
        for (int d = 0; d < 8; d++) {
            o[d][0] *= a0; o[d][1] *= a0;
            o[d][2] *= a1; o[d][3] *= a1;
        }
#pragma unroll
        for (int ot = 0; ot < 8; ot++) {
            float p0 = __expf(s[ot][0] - mn0);
            float p1 = __expf(s[ot][1] - mn0);
            float p2 = __expf(s[ot][2] - mn1);
            float p3 = __expf(s[ot][3] - mn1);
            l0 += p0 + p1; l1 += p2 + p3;
            s[ot][0] = p0; s[ot][1] = p1; s[ot][2] = p2; s[ot][3] = p3;
        }

        // ---- O += P V ----
#pragma unroll
        for (int kt = 0; kt < 4; kt++) {
            float p00 = s[2 * kt][0],     p01 = s[2 * kt][1];
            float p10 = s[2 * kt][2],     p11 = s[2 * kt][3];
            float r00 = s[2 * kt + 1][0], r01 = s[2 * kt + 1][1];
            float r10 = s[2 * kt + 1][2], r11 = s[2 * kt + 1][3];
            float h00 = bf16rf(p00), h01 = bf16rf(p01), h10 = bf16rf(p10), h11 = bf16rf(p11);
            float g00 = bf16rf(r00), g01 = bf16rf(r01), g10 = bf16rf(r10), g11 = bf16rf(r11);
            uint32_t aph[4] = { packbf(p00, p01), packbf(p10, p11),
                                packbf(r00, r01), packbf(r10, r11) };
            uint32_t apl[4] = { packbf(p00 - h00, p01 - h01), packbf(p10 - h10, p11 - h11),
                                packbf(r00 - g00, r01 - g01), packbf(r10 - g10, r11 - g11) };
            uint32_t vh[4][4], vl[4][4];
#pragma unroll
            for (int dt = 0; dt < 4; dt++) {
                uint32_t ro = (kt * 16 + (lane & 15)) * 128 + dt * 32 + (lane >> 4) * 16;
                ldsm4t(vh[dt], kvb + 16384 + SW128(ro));
                ldsm4t(vl[dt], kvb + 24576 + SW128(ro));
            }
#pragma unroll
            for (int dt = 0; dt < 4; dt++) {
                mma16816(o[2 * dt],     aph, vh[dt][0], vh[dt][1]);
                mma16816(o[2 * dt + 1], aph, vh[dt][2], vh[dt][3]);
            }
#pragma unroll
            for (int dt = 0; dt < 4; dt++) {
                mma16816(o[2 * dt],     aph, vl[dt][0], vl[dt][1]);
                mma16816(o[2 * dt + 1], aph, vl[dt][2], vl[dt][3]);
            }
#pragma unroll
            for (int dt = 0; dt < 4; dt++) {
                mma16816(o[2 * dt],     apl, vh[dt][0], vh[dt][1]);
                mma16816(o[2 * dt + 1], apl, vh[dt][2], vh[dt][3]);
            }
        }
    }

    // ---- finalize ----
    l0 += __shfl_xor_sync(0xffffffff, l0, 1);
    l0 += __shfl_xor_sync(0xffffffff, l0, 2);
    l1 += __shfl_xor_sync(0xffffffff, l1, 1);
    l1 += __shfl_xor_sync(0xffffffff, l1, 2);
    const float i0 = 1.f / l0, i1 = 1.f / l1;

    const int row0 = q0 + w * 16 + rA;
    const int cb   = h * 64 + (lane & 3) * 2;
#pragma unroll
    for (int d = 0; d < 8; d++) {
        int col = cb + d * 8;
        float v0 = o[d][0] * i0, v1 = o[d][1] * i0;
        float v2 = o[d][2] * i1, v3 = o[d][3] * i1;
        float h0 = bf16rf(v0), h1 = bf16rf(v1), h2 = bf16rf(v2), h3 = bf16rf(v3);
        *(uint32_t*)&g_yh[(size_t)row0 * C_DIM + col]       = packbf(v0, v1);
        *(uint32_t*)&g_yl[(size_t)row0 * C_DIM + col]       = packbf(v0 - h0, v1 - h1);
        *(uint32_t*)&g_yh[(size_t)(row0 + 8) * C_DIM + col] = packbf(v2, v3);
        *(uint32_t*)&g_yl[(size_t)(row0 + 8) * C_DIM + col] = packbf(v2 - h2, v3 - h3);
    }
}

// ---------------------------------------------------------------------------
extern "C" void kernel_launch(void* const* d_in, const int* in_sizes, int n_in,
                              void* d_out, int out_size)
{
    const float* x      = (const float*)d_in[0];
    const float* w_attn = (const float*)d_in[1];
    const float* w_proj = (const float*)d_in[2];
    float* out = (float*)d_out;
    (void)in_sizes; (void)n_in; (void)out_size;

    cudaFuncSetAttribute(gemm_kernel<true>,
                         cudaFuncAttributeMaxDynamicSharedMemorySize, GEMM_SMEM);
    cudaFuncSetAttribute(gemm_kernel<false>,
                         cudaFuncAttributeMaxDynamicSharedMemorySize, GEMM_SMEM);
    cudaFuncSetAttribute(attn_kernel,
                         cudaFuncAttributeMaxDynamicSharedMemorySize, ATTN_SMEM);

    void *p_xh, *p_xl, *p_wah, *p_wal, *p_wph, *p_wpl, *p_qh, *p_ql, *p_yh, *p_yl;
    cudaGetSymbolAddress(&p_xh, g_xh);   cudaGetSymbolAddress(&p_xl, g_xl);
    cudaGetSymbolAddress(&p_wah, g_wah); cudaGetSymbolAddress(&p_wal, g_wal);
    cudaGetSymbolAddress(&p_wph, g_wph); cudaGetSymbolAddress(&p_wpl, g_wpl);
    cudaGetSymbolAddress(&p_qh, g_qkvh); cudaGetSymbolAddress(&p_ql, g_qkvl);
    cudaGetSymbolAddress(&p_yh, g_yh);   cudaGetSymbolAddress(&p_yl, g_yl);

    // 1) split inputs
    cvt_split_kernel<<<T_SEQ * C_DIM / 4 / 256, 256>>>(
        x, (__nv_bfloat16*)p_xh, (__nv_bfloat16*)p_xl, T_SEQ * C_DIM / 4);
    cvt_split_kernel<<<F_DIM * C_DIM / 4 / 256, 256>>>(
        w_attn, (__nv_bfloat16*)p_wah, (__nv_bfloat16*)p_wal, F_DIM * C_DIM / 4);
    cvt_split_kernel<<<C_DIM * C_DIM / 4 / 256, 256>>>(
        w_proj, (__nv_bfloat16*)p_wph, (__nv_bfloat16*)p_wpl, C_DIM * C_DIM / 4);

    // 2) qkv = x @ w_attn^T  -> split bf16 output
    gemm_kernel<true><<<dim3(F_DIM / 256, T_SEQ / 128), 512, GEMM_SMEM>>>(
        (const __nv_bfloat16*)p_xh, (const __nv_bfloat16*)p_xl,
        (const __nv_bfloat16*)p_wah, (const __nv_bfloat16*)p_wal,
        nullptr, (__nv_bfloat16*)p_qh, (__nv_bfloat16*)p_ql, C_DIM, F_DIM);

    // 3) tensor-core causal attention -> split bf16 y
    attn_kernel<<<dim3(T_SEQ / 128, H_NUM), 256, ATTN_SMEM>>>();

    // 4) out = y @ w_proj^T  (fp32 output)
    gemm_kernel<false><<<dim3(C_DIM / 256, T_SEQ / 128), 512, GEMM_SMEM>>>(
        (const __nv_bfloat16*)p_yh, (const __nv_bfloat16*)p_yl,
        (const __nv_bfloat16*)p_wph, (const __nv_bfloat16*)p_wpl,
        out, nullptr, nullptr, C_DIM, C_DIM);
}

// round 11
// speedup vs baseline: 14.6817x; 2.1625x over previous
#include <cuda_runtime.h>
#include <cuda_fp16.h>
#include <cstdint>

#define T_SEQ  4096
#define C_DIM  1024
#define H_NUM  16
#define D_HEAD 64
#define F_DIM  3072

// ---------------------------------------------------------------------------
// Device globals (no allocations allowed) — single fp16 copies
// ---------------------------------------------------------------------------
__device__ __half g_x[T_SEQ * C_DIM];
__device__ __half g_wa[F_DIM * C_DIM];
__device__ __half g_wp[C_DIM * C_DIM];
__device__ __half g_qkv[(size_t)T_SEQ * F_DIM];
__device__ __half g_y[T_SEQ * C_DIM];

// ---------------------------------------------------------------------------
// Helpers
// ---------------------------------------------------------------------------
__device__ __forceinline__ uint32_t s2u(const void* p) {
    uint32_t a;
    asm("{ .reg .u64 t; cvta.to.shared.u64 t, %1; cvt.u32.u64 %0, t; }"
        : "=r"(a) : "l"(p));
    return a;
}
#define SW128(o) ((uint32_t)(o) ^ ((((uint32_t)(o)) >> 3) & 0x70))

__device__ __forceinline__ void ldsm4(uint32_t* r, uint32_t addr) {
    asm volatile("ldmatrix.sync.aligned.m8n8.x4.shared.b16 {%0,%1,%2,%3}, [%4];"
                 : "=r"(r[0]), "=r"(r[1]), "=r"(r[2]), "=r"(r[3]) : "r"(addr));
}
__device__ __forceinline__ void ldsm4t(uint32_t* r, uint32_t addr) {
    asm volatile("ldmatrix.sync.aligned.m8n8.x4.trans.shared.b16 {%0,%1,%2,%3}, [%4];"
                 : "=r"(r[0]), "=r"(r[1]), "=r"(r[2]), "=r"(r[3]) : "r"(addr));
}
__device__ __forceinline__ void mma16816(float* c, const uint32_t* a,
                                         uint32_t b0, uint32_t b1) {
    asm volatile("mma.sync.aligned.m16n8k16.row.col.f32.f16.f16.f32 "
                 "{%0,%1,%2,%3}, {%4,%5,%6,%7}, {%8,%9}, {%0,%1,%2,%3};"
                 : "+f"(c[0]), "+f"(c[1]), "+f"(c[2]), "+f"(c[3])
                 : "r"(a[0]), "r"(a[1]), "r"(a[2]), "r"(a[3]), "r"(b0), "r"(b1));
}
#define CP16(s, g)  asm volatile("cp.async.cg.shared.global [%0], [%1], 16;" :: "r"(s), "l"(g))
#define CPCOMMIT()  asm volatile("cp.async.commit_group;" ::: "memory")
#define CPWAIT1()   asm volatile("cp.async.wait_group 1;" ::: "memory")
#define CPWAIT0()   asm volatile("cp.async.wait_group 0;" ::: "memory")

__device__ __forceinline__ uint32_t packh(float a, float b) {
    __half2 t = __floats2half2_rn(a, b);
    return reinterpret_cast<uint32_t&>(t);
}

// ---------------------------------------------------------------------------
// fp32 -> fp16 convert
// ---------------------------------------------------------------------------
__global__ __launch_bounds__(256)
void cvt_f16_kernel(const float* __restrict__ in, __half* __restrict__ out, int n4)
{
    int i = blockIdx.x * 256 + threadIdx.x;
    if (i >= n4) return;
    float4 v = ((const float4*)in)[i];
    ((uint32_t*)out)[2 * i]     = packh(v.x, v.y);
    ((uint32_t*)out)[2 * i + 1] = packh(v.z, v.w);
}

// ---------------------------------------------------------------------------
// fp16 GEMM:  C[M,N] = sum_k A[m,k]*B[n,k].  BM=128, BN=256, BK=64.
// 512 threads (16 warps: 4 along M x 4 along N, warp tile 32x64).
// 2-stage cp.async pipeline.  HALF_OUT: write fp16 C, else fp32.
// ---------------------------------------------------------------------------
#define OA 0
#define OB 16384         // B: 256 rows * 128B = 32KB
#define GST 49152        // 48KB stage
#define GEMM_SMEM (2 * GST + 1024)

template<bool HALF_OUT>
__global__ __launch_bounds__(512, 1)
void gemm_kernel(const __half* __restrict__ A,
                 const __half* __restrict__ B,
                 float* __restrict__ Cout,
                 __half* __restrict__ Ch,
                 int K, int N)
{
    extern __shared__ char smraw[];
    const uint32_t sb = (s2u(smraw) + 1023u) & ~1023u;
    const int tid  = threadIdx.x;
    const int lane = tid & 31;
    const int w    = tid >> 5;
    const int wm   = w & 3;        // 0..3 along M (32 rows each)
    const int wn   = w >> 2;       // 0..3 along N (64 cols each)
    const int m0   = blockIdx.y * 128;
    const int n0   = blockIdx.x * 256;

    auto load_stage = [&](int stage, int kt) {
        const uint32_t s0 = sb + stage * GST;
        const int kk = kt * 64;
#pragma unroll
        for (int it = 0; it < 2; it++) {
            int idx = tid + it * 512;           // 0..1023
            int r = idx >> 3, q = idx & 7;
            uint32_t so = SW128(r * 128 + q * 16);
            CP16(s0 + OA + so, (const void*)(A + (size_t)(m0 + r) * K + kk + q * 8));
        }
#pragma unroll
        for (int it = 0; it < 4; it++) {
            int idx = tid + it * 512;           // 0..2047
            int r = idx >> 3, q = idx & 7;
            uint32_t so = SW128(r * 128 + q * 16);
            CP16(s0 + OB + so, (const void*)(B + (size_t)(n0 + r) * K + kk + q * 8));
        }
        CPCOMMIT();
    };

    float c[2][8][4];
#pragma unroll
    for (int mt = 0; mt < 2; mt++)
#pragma unroll
        for (int o = 0; o < 8; o++)
#pragma unroll
            for (int e = 0; e < 4; e++) c[mt][o][e] = 0.f;

    const int nT = K / 64;
    load_stage(0, 0);
    load_stage(1, 1);

    for (int t = 0; t < nT; t++) {
        if (t + 1 < nT) CPWAIT1(); else CPWAIT0();
        __syncthreads();
        const uint32_t s0 = sb + (t & 1) * GST;

#pragma unroll
        for (int ks = 0; ks < 4; ks++) {
            const uint32_t kb = ks * 32 + (lane >> 4) * 16;
            uint32_t ah[2][4];
#pragma unroll
            for (int mt = 0; mt < 2; mt++) {
                uint32_t ro = (wm * 32 + mt * 16 + (lane & 15)) * 128 + kb;
                ldsm4(ah[mt], s0 + OA + SW128(ro));
            }
            uint32_t bh[4][4];
#pragma unroll
            for (int nt = 0; nt < 4; nt++) {
                uint32_t ro = (wn * 64 + nt * 16 + (lane & 15)) * 128 + kb;
                ldsm4(bh[nt], s0 + OB + SW128(ro));
            }
#pragma unroll
            for (int mt = 0; mt < 2; mt++)
#pragma unroll
                for (int nt = 0; nt < 4; nt++) {
                    mma16816(c[mt][2 * nt],     ah[mt], bh[nt][0], bh[nt][2]);
                    mma16816(c[mt][2 * nt + 1], ah[mt], bh[nt][1], bh[nt][3]);
                }
        }
        __syncthreads();
        if (t + 2 < nT) load_stage(t & 1, t + 2);
    }

    // ---- epilogue ----
    const int rbase = m0 + wm * 32 + (lane >> 2);
    const int cbase = n0 + wn * 64 + (lane & 3) * 2;
#pragma unroll
    for (int mt = 0; mt < 2; mt++) {
#pragma unroll
        for (int o = 0; o < 8; o++) {
            int col = cbase + o * 8;
            int r0 = rbase + mt * 16;
            int r1 = r0 + 8;
            if (HALF_OUT) {
                *(uint32_t*)&Ch[(size_t)r0 * N + col] = packh(c[mt][o][0], c[mt][o][1]);
                *(uint32_t*)&Ch[(size_t)r1 * N + col] = packh(c[mt][o][2], c[mt][o][3]);
            } else {
                *(float2*)&Cout[(size_t)r0 * N + col] = make_float2(c[mt][o][0], c[mt][o][1]);
                *(float2*)&Cout[(size_t)r1 * N + col] = make_float2(c[mt][o][2], c[mt][o][3]);
            }
        }
    }
}

// ---------------------------------------------------------------------------
// Tensor-core causal flash attention, fp16, cp.async 3-buffer KV pipeline.
// Block: 256 threads (8 warps), Q tile = 128 rows (warp w: rows w*16..+15),
// KV tile = 64 keys.  Smem: Q(16K) | 3 x [K 8K | V 8K]
// ---------------------------------------------------------------------------
#define AQ  0
#define AKV 16384
#define KVB 16384                       // per-buffer size (K 8K + V 8K)
#define ATTN_SMEM (AKV + 3 * KVB + 1024)

__global__ __launch_bounds__(256, 2)
void attn_kernel()
{
    extern __shared__ char smraw[];
    const uint32_t sb = (s2u(smraw) + 1023u) & ~1023u;
    const int qt   = (int)gridDim.x - 1 - (int)blockIdx.x;   // heavy tiles first
    const int h    = blockIdx.y;
    const int q0   = qt * 128;
    const int tid  = threadIdx.x;
    const int w    = tid >> 5;
    const int lane = tid & 31;
    const int ntiles = 2 * qt + 2;

    auto load_kv = [&](int buf, int j) {
        const int k0 = j * 64;
        const uint32_t b0 = sb + AKV + buf * KVB;
#pragma unroll
        for (int it = 0; it < 4; it++) {
            int idx = tid + it * 256;       // 0..1023
            int arr = idx >> 9;             // 0:K 1:V
            int rem = idx & 511;
            int r = rem >> 3, q = rem & 7;
            uint32_t so = SW128(r * 128 + q * 16) + arr * 8192;
            size_t go = (size_t)(k0 + r) * F_DIM + (arr ? 2 * C_DIM : C_DIM) + h * 64 + q * 8;
            CP16(b0 + so, (const void*)(g_qkv + go));
        }
        CPCOMMIT();
    };

    // prefetch KV tile 0 (overlaps Q staging)
    load_kv(0, 0);

    // ---- stage Q tile ----
#pragma unroll
    for (int it = 0; it < 4; it++) {
        int idx = tid + it * 256;            // 0..1023
        int r = idx >> 3, q = idx & 7;
        size_t go = (size_t)(q0 + r) * F_DIM + h * 64 + q * 8;
        uint32_t so = SW128(r * 128 + q * 16);
        uint4 vh = *(const uint4*)&g_qkv[go];
        asm volatile("st.shared.v4.b32 [%0],{%1,%2,%3,%4};"
                     :: "r"(sb + AQ + so), "r"(vh.x), "r"(vh.y), "r"(vh.z), "r"(vh.w));
    }
    __syncthreads();

    // Q fragments (A operand), rows w*16..w*16+15, per k16 step
    uint32_t qh[4][4];
#pragma unroll
    for (int ks = 0; ks < 4; ks++) {
        uint32_t ro = (w * 16 + (lane & 15)) * 128 + ks * 32 + (lane >> 4) * 16;
        ldsm4(qh[ks], sb + AQ + SW128(ro));
    }

    float o[8][4];
#pragma unroll
    for (int d = 0; d < 8; d++)
#pragma unroll
        for (int e = 0; e < 4; e++) o[d][e] = 0.f;
    float m0v = -1e30f, m1v = -1e30f, l0 = 0.f, l1 = 0.f;

    const int rA = lane >> 2;
    const int wrow_min = q0 + w * 16;
    const int wrow_max = wrow_min + 15;

    for (int j = 0; j < ntiles; j++) {
        const int k0 = j * 64;
        if (j + 1 < ntiles) load_kv((j + 1) % 3, j + 1);
        if (j + 1 < ntiles) CPWAIT1(); else CPWAIT0();
        __syncthreads();

        if (k0 > wrow_max) continue;        // fully masked for this warp

        const uint32_t kvb = sb + AKV + (j % 3) * KVB;

        // ---- S = Q K^T ----
        float s[8][4];
#pragma unroll
        for (int ot = 0; ot < 8; ot++)
#pragma unroll
            for (int e = 0; e < 4; e++) s[ot][e] = 0.f;
#pragma unroll
        for (int ks = 0; ks < 4; ks++) {
            uint32_t kh[4][4];
#pragma unroll
            for (int nt = 0; nt < 4; nt++) {
                uint32_t ro = (nt * 16 + (lane & 15)) * 128 + ks * 32 + (lane >> 4) * 16;
                ldsm4(kh[nt], kvb + SW128(ro));
            }
#pragma unroll
            for (int nt = 0; nt < 4; nt++) {
                mma16816(s[2 * nt],     qh[ks], kh[nt][0], kh[nt][2]);
                mma16816(s[2 * nt + 1], qh[ks], kh[nt][1], kh[nt][3]);
            }
        }

        // ---- scale + causal mask ----
        const bool need_mask = (k0 + 63 > wrow_min);
#pragma unroll
        for (int ot = 0; ot < 8; ot++)
#pragma unroll
            for (int e = 0; e < 4; e++) {
                float v = s[ot][e] * 0.125f;
                if (need_mask) {
                    int n = k0 + ot * 8 + (lane & 3) * 2 + (e & 1);
                    int r = wrow_min + rA + ((e >= 2) ? 8 : 0);
                    if (n > r) v = -1e30f;
                }
                s[ot][e] = v;
            }

        // ---- online softmax ----
        float mx0 = -1e30f, mx1 = -1e30f;
#pragma unroll
        for (int ot = 0; ot < 8; ot++) {
            mx0 = fmaxf(mx0, fmaxf(s[ot][0], s[ot][1]));
            mx1 = fmaxf(mx1, fmaxf(s[ot][2], s[ot][3]));
        }
        mx0 = fmaxf(mx0, __shfl_xor_sync(0xffffffff, mx0, 1));
        mx0 = fmaxf(mx0, __shfl_xor_sync(0xffffffff, mx0, 2));
        mx1 = fmaxf(mx1, __shfl_xor_sync(0xffffffff, mx1, 1));
        mx1 = fmaxf(mx1, __shfl_xor_sync(0xffffffff, mx1, 2));

        float mn0 = fmaxf(m0v, mx0), mn1 = fmaxf(m1v, mx1);
        float a0 = __expf(m0v - mn0), a1 = __expf(m1v - mn1);
        m0v = mn0; m1v = mn1;
        l0 *= a0;  l1 *= a1;
#pragma unroll
        for (int d = 0; d < 8; d++) {
            o[d][0] *= a0; o[d][1] *= a0;
            o[d][2] *= a1; o[d][3] *= a1;
        }
#pragma unroll
        for (int ot = 0; ot < 8; ot++) {
            float p0 = __expf(s[ot][0] - mn0);
            float p1 = __expf(s[ot][1] - mn0);
            float p2 = __expf(s[ot][2] - mn1);
            float p3 = __expf(s[ot][3] - mn1);
            l0 += p0 + p1; l1 += p2 + p3;
            s[ot][0] = p0; s[ot][1] = p1; s[ot][2] = p2; s[ot][3] = p3;
        }

        // ---- O += P V  (P packed fp16 in regs, V via ldmatrix.trans) ----
#pragma unroll
        for (int kt = 0; kt < 4; kt++) {
            uint32_t ap[4] = {
                packh(s[2 * kt][0],     s[2 * kt][1]),
                packh(s[2 * kt][2],     s[2 * kt][3]),
                packh(s[2 * kt + 1][0], s[2 * kt + 1][1]),
                packh(s[2 * kt + 1][2], s[2 * kt + 1][3])
            };
            uint32_t vh[4][4];
#pragma unroll
            for (int dt = 0; dt < 4; dt++) {
                uint32_t ro = (kt * 16 + (lane & 15)) * 128 + dt * 32 + (lane >> 4) * 16;
                ldsm4t(vh[dt], kvb + 8192 + SW128(ro));
            }
#pragma unroll
            for (int dt = 0; dt < 4; dt++) {
                mma16816(o[2 * dt],     ap, vh[dt][0], vh[dt][1]);
                mma16816(o[2 * dt + 1], ap, vh[dt][2], vh[dt][3]);
            }
        }
    }

    // ---- finalize ----
    l0 += __shfl_xor_sync(0xffffffff, l0, 1);
    l0 += __shfl_xor_sync(0xffffffff, l0, 2);
    l1 += __shfl_xor_sync(0xffffffff, l1, 1);
    l1 += __shfl_xor_sync(0xffffffff, l1, 2);
    const float i0 = 1.f / l0, i1 = 1.f / l1;

    const int row0 = q0 + w * 16 + rA;
    const int cb   = h * 64 + (lane & 3) * 2;
#pragma unroll
    for (int d = 0; d < 8; d++) {
        int col = cb + d * 8;
        *(uint32_t*)&g_y[(size_t)row0 * C_DIM + col]       = packh(o[d][0] * i0, o[d][1] * i0);
        *(uint32_t*)&g_y[(size_t)(row0 + 8) * C_DIM + col] = packh(o[d][2] * i1, o[d][3] * i1);
    }
}

// ---------------------------------------------------------------------------
extern "C" void kernel_launch(void* const* d_in, const int* in_sizes, int n_in,
                              void* d_out, int out_size)
{
    const float* x      = (const float*)d_in[0];
    const float* w_attn = (const float*)d_in[1];
    const float* w_proj = (const float*)d_in[2];
    float* out = (float*)d_out;
    (void)in_sizes; (void)n_in; (void)out_size;

    cudaFuncSetAttribute(gemm_kernel<true>,
                         cudaFuncAttributeMaxDynamicSharedMemorySize, GEMM_SMEM);
    cudaFuncSetAttribute(gemm_kernel<false>,
                         cudaFuncAttributeMaxDynamicSharedMemorySize, GEMM_SMEM);
    cudaFuncSetAttribute(attn_kernel,
                         cudaFuncAttributeMaxDynamicSharedMemorySize, ATTN_SMEM);

    void *p_x, *p_wa, *p_wp, *p_qkv, *p_y;
    cudaGetSymbolAddress(&p_x, g_x);
    cudaGetSymbolAddress(&p_wa, g_wa);
    cudaGetSymbolAddress(&p_wp, g_wp);
    cudaGetSymbolAddress(&p_qkv, g_qkv);
    cudaGetSymbolAddress(&p_y, g_y);

    // 1) convert inputs to fp16
    cvt_f16_kernel<<<T_SEQ * C_DIM / 4 / 256, 256>>>(x, (__half*)p_x, T_SEQ * C_DIM / 4);
    cvt_f16_kernel<<<F_DIM * C_DIM / 4 / 256, 256>>>(w_attn, (__half*)p_wa, F_DIM * C_DIM / 4);
    cvt_f16_kernel<<<C_DIM * C_DIM / 4 / 256, 256>>>(w_proj, (__half*)p_wp, C_DIM * C_DIM / 4);

    // 2) qkv = x @ w_attn^T  -> fp16
    gemm_kernel<true><<<dim3(F_DIM / 256, T_SEQ / 128), 512, GEMM_SMEM>>>(
        (const __half*)p_x, (const __half*)p_wa,
        nullptr, (__half*)p_qkv, C_DIM, F_DIM);

    // 3) tensor-core causal attention -> fp16 y
    attn_kernel<<<dim3(T_SEQ / 128, H_NUM), 256, ATTN_SMEM>>>();

    // 4) out = y @ w_proj^T  (fp32 output)
    gemm_kernel<false><<<dim3(C_DIM / 256, T_SEQ / 128), 512, GEMM_SMEM>>>(
        (const __half*)p_y, (const __half*)p_wp,
        out, nullptr, C_DIM, C_DIM);
}

// round 12
// speedup vs baseline: 15.6531x; 1.0662x over previous
#include <cuda_runtime.h>
#include <cuda_fp16.h>
#include <cstdint>

#define T_SEQ  4096
#define C_DIM  1024
#define H_NUM  16
#define D_HEAD 64
#define F_DIM  3072

// ---------------------------------------------------------------------------
// Device globals (no allocations allowed)
// ---------------------------------------------------------------------------
__device__ __half g_x[T_SEQ * C_DIM];
__device__ __half g_wa[F_DIM * C_DIM];
__device__ __half g_wp[C_DIM * C_DIM];
__device__ __half g_qkv[(size_t)T_SEQ * F_DIM];
__device__ __half g_y[T_SEQ * C_DIM];

// ---------------------------------------------------------------------------
// Helpers
// ---------------------------------------------------------------------------
__device__ __forceinline__ uint32_t s2u(const void* p) {
    uint32_t a;
    asm("{ .reg .u64 t; cvta.to.shared.u64 t, %1; cvt.u32.u64 %0, t; }"
        : "=r"(a) : "l"(p));
    return a;
}
#define SW128(o) ((uint32_t)(o) ^ ((((uint32_t)(o)) >> 3) & 0x70))

__device__ __forceinline__ void ldsm4(uint32_t* r, uint32_t addr) {
    asm volatile("ldmatrix.sync.aligned.m8n8.x4.shared.b16 {%0,%1,%2,%3}, [%4];"
                 : "=r"(r[0]), "=r"(r[1]), "=r"(r[2]), "=r"(r[3]) : "r"(addr));
}
__device__ __forceinline__ void ldsm4t(uint32_t* r, uint32_t addr) {
    asm volatile("ldmatrix.sync.aligned.m8n8.x4.trans.shared.b16 {%0,%1,%2,%3}, [%4];"
                 : "=r"(r[0]), "=r"(r[1]), "=r"(r[2]), "=r"(r[3]) : "r"(addr));
}
__device__ __forceinline__ void mma16816(float* c, const uint32_t* a,
                                         uint32_t b0, uint32_t b1) {
    asm volatile("mma.sync.aligned.m16n8k16.row.col.f32.f16.f16.f32 "
                 "{%0,%1,%2,%3}, {%4,%5,%6,%7}, {%8,%9}, {%0,%1,%2,%3};"
                 : "+f"(c[0]), "+f"(c[1]), "+f"(c[2]), "+f"(c[3])
                 : "r"(a[0]), "r"(a[1]), "r"(a[2]), "r"(a[3]), "r"(b0), "r"(b1));
}
#define CP16(s, g)  asm volatile("cp.async.cg.shared.global [%0], [%1], 16;" :: "r"(s), "l"(g))
#define CPCOMMIT()  asm volatile("cp.async.commit_group;" ::: "memory")
#define CPWAIT1()   asm volatile("cp.async.wait_group 1;" ::: "memory")
#define CPWAIT0()   asm volatile("cp.async.wait_group 0;" ::: "memory")

__device__ __forceinline__ uint32_t packh(float a, float b) {
    __half2 t = __floats2half2_rn(a, b);
    return reinterpret_cast<uint32_t&>(t);
}

// ---------------------------------------------------------------------------
// Fused fp32 -> fp16 convert for x, w_attn, w_proj in ONE launch.
// Block ranges: [0,4096) -> x (1,048,576 float4), [4096,7168) -> w_attn,
// [7168,8192) -> w_proj.
// ---------------------------------------------------------------------------
__global__ __launch_bounds__(256)
void cvt_all_kernel(const float* __restrict__ x,
                    const float* __restrict__ wa,
                    const float* __restrict__ wp)
{
    int b = blockIdx.x;
    const float* in;
    __half* out;
    int i;
    if (b < 4096)      { in = x;  out = g_x;  i = b * 256 + threadIdx.x; }
    else if (b < 7168) { in = wa; out = g_wa; i = (b - 4096) * 256 + threadIdx.x; }
    else               { in = wp; out = g_wp; i = (b - 7168) * 256 + threadIdx.x; }
    float4 v = ((const float4*)in)[i];
    ((uint32_t*)out)[2 * i]     = packh(v.x, v.y);
    ((uint32_t*)out)[2 * i + 1] = packh(v.z, v.w);
}

// ---------------------------------------------------------------------------
// fp16 GEMM:  C[M,N] = sum_k A[m,k]*B[n,k].  BM=128, BN=256, BK=64.
// 256 threads (8 warps: 2 along M x 4 along N, warp tile 64x64).
// LDSM:MMA ratio 0.25.  2-stage cp.async pipeline.
// ---------------------------------------------------------------------------
#define OA 0
#define OB 16384         // B: 256 rows * 128B = 32KB
#define GST 49152        // 48KB stage
#define GEMM_SMEM (2 * GST + 1024)

template<bool HALF_OUT>
__global__ __launch_bounds__(256, 1)
void gemm_kernel(const __half* __restrict__ A,
                 const __half* __restrict__ B,
                 float* __restrict__ Cout,
                 __half* __restrict__ Ch,
                 int K, int N)
{
    extern __shared__ char smraw[];
    const uint32_t sb = (s2u(smraw) + 1023u) & ~1023u;
    const int tid  = threadIdx.x;
    const int lane = tid & 31;
    const int w    = tid >> 5;
    const int wm   = w & 1;        // 0..1 along M (64 rows each)
    const int wn   = w >> 1;       // 0..3 along N (64 cols each)
    const int m0   = blockIdx.y * 128;
    const int n0   = blockIdx.x * 256;

    auto load_stage = [&](int stage, int kt) {
        const uint32_t s0 = sb + stage * GST;
        const int kk = kt * 64;
#pragma unroll
        for (int it = 0; it < 4; it++) {
            int idx = tid + it * 256;           // 0..1023
            int r = idx >> 3, q = idx & 7;
            uint32_t so = SW128(r * 128 + q * 16);
            CP16(s0 + OA + so, (const void*)(A + (size_t)(m0 + r) * K + kk + q * 8));
        }
#pragma unroll
        for (int it = 0; it < 8; it++) {
            int idx = tid + it * 256;           // 0..2047
            int r = idx >> 3, q = idx & 7;
            uint32_t so = SW128(r * 128 + q * 16);
            CP16(s0 + OB + so, (const void*)(B + (size_t)(n0 + r) * K + kk + q * 8));
        }
        CPCOMMIT();
    };

    float c[4][8][4];
#pragma unroll
    for (int mt = 0; mt < 4; mt++)
#pragma unroll
        for (int o = 0; o < 8; o++)
#pragma unroll
            for (int e = 0; e < 4; e++) c[mt][o][e] = 0.f;

    const int nT = K / 64;
    load_stage(0, 0);
    load_stage(1, 1);

    for (int t = 0; t < nT; t++) {
        if (t + 1 < nT) CPWAIT1(); else CPWAIT0();
        __syncthreads();
        const uint32_t s0 = sb + (t & 1) * GST;

#pragma unroll
        for (int ks = 0; ks < 4; ks++) {
            const uint32_t kb = ks * 32 + (lane >> 4) * 16;
            uint32_t ah[4][4];
#pragma unroll
            for (int mt = 0; mt < 4; mt++) {
                uint32_t ro = (wm * 64 + mt * 16 + (lane & 15)) * 128 + kb;
                ldsm4(ah[mt], s0 + OA + SW128(ro));
            }
            uint32_t bh[4][4];
#pragma unroll
            for (int nt = 0; nt < 4; nt++) {
                uint32_t ro = (wn * 64 + nt * 16 + (lane & 15)) * 128 + kb;
                ldsm4(bh[nt], s0 + OB + SW128(ro));
            }
#pragma unroll
            for (int mt = 0; mt < 4; mt++)
#pragma unroll
                for (int nt = 0; nt < 4; nt++) {
                    mma16816(c[mt][2 * nt],     ah[mt], bh[nt][0], bh[nt][2]);
                    mma16816(c[mt][2 * nt + 1], ah[mt], bh[nt][1], bh[nt][3]);
                }
        }
        __syncthreads();
        if (t + 2 < nT) load_stage(t & 1, t + 2);
    }

    // ---- epilogue ----
    const int rbase = m0 + wm * 64 + (lane >> 2);
    const int cbase = n0 + wn * 64 + (lane & 3) * 2;
#pragma unroll
    for (int mt = 0; mt < 4; mt++) {
#pragma unroll
        for (int o = 0; o < 8; o++) {
            int col = cbase + o * 8;
            int r0 = rbase + mt * 16;
            int r1 = r0 + 8;
            if (HALF_OUT) {
                *(uint32_t*)&Ch[(size_t)r0 * N + col] = packh(c[mt][o][0], c[mt][o][1]);
                *(uint32_t*)&Ch[(size_t)r1 * N + col] = packh(c[mt][o][2], c[mt][o][3]);
            } else {
                *(float2*)&Cout[(size_t)r0 * N + col] = make_float2(c[mt][o][0], c[mt][o][1]);
                *(float2*)&Cout[(size_t)r1 * N + col] = make_float2(c[mt][o][2], c[mt][o][3]);
            }
        }
    }
}

// ---------------------------------------------------------------------------
// Tensor-core causal flash attention, fp16, cp.async 3-buffer KV pipeline.
// Block: 128 threads (4 warps), warp owns 32 q-rows (q-tile 128).
// 2 CTAs/SM.  KV tile = 64 keys.  Smem: Q(16K) | 3 x [K 8K | V 8K]
// ---------------------------------------------------------------------------
#define AQ  0
#define AKV 16384
#define KVB 16384
#define ATTN_SMEM (AKV + 3 * KVB + 1024)

// log2(e) / sqrt(64)
#define QK_SCALE 0.1803368801111244f

__global__ __launch_bounds__(128, 2)
void attn_kernel()
{
    extern __shared__ char smraw[];
    const uint32_t sb = (s2u(smraw) + 1023u) & ~1023u;
    const int qt   = (int)gridDim.x - 1 - (int)blockIdx.x;   // heavy tiles first
    const int h    = blockIdx.y;
    const int q0   = qt * 128;
    const int tid  = threadIdx.x;
    const int w    = tid >> 5;
    const int lane = tid & 31;
    const int ntiles = 2 * qt + 2;

    auto load_kv = [&](int buf, int j) {
        const int k0 = j * 64;
        const uint32_t b0 = sb + AKV + buf * KVB;
#pragma unroll
        for (int it = 0; it < 8; it++) {
            int idx = tid + it * 128;       // 0..1023
            int arr = idx >> 9;             // 0:K 1:V
            int rem = idx & 511;
            int r = rem >> 3, q = rem & 7;
            uint32_t so = SW128(r * 128 + q * 16) + arr * 8192;
            size_t go = (size_t)(k0 + r) * F_DIM + (arr ? 2 * C_DIM : C_DIM) + h * 64 + q * 8;
            CP16(b0 + so, (const void*)(g_qkv + go));
        }
        CPCOMMIT();
    };

    load_kv(0, 0);

    // ---- stage Q tile (128 rows) ----
#pragma unroll
    for (int it = 0; it < 8; it++) {
        int idx = tid + it * 128;            // 0..1023
        int r = idx >> 3, q = idx & 7;
        size_t go = (size_t)(q0 + r) * F_DIM + h * 64 + q * 8;
        uint32_t so = SW128(r * 128 + q * 16);
        uint4 vh = *(const uint4*)&g_qkv[go];
        asm volatile("st.shared.v4.b32 [%0],{%1,%2,%3,%4};"
                     :: "r"(sb + AQ + so), "r"(vh.x), "r"(vh.y), "r"(vh.z), "r"(vh.w));
    }
    __syncthreads();

    // Q fragments: warp rows w*32 .. w*32+31 (2 m-tiles of 16), per k16 step
    uint32_t qh[4][2][4];
#pragma unroll
    for (int ks = 0; ks < 4; ks++)
#pragma unroll
        for (int mt = 0; mt < 2; mt++) {
            uint32_t ro = (w * 32 + mt * 16 + (lane & 15)) * 128 + ks * 32 + (lane >> 4) * 16;
            ldsm4(qh[ks][mt], sb + AQ + SW128(ro));
        }

    float o[2][8][4];
#pragma unroll
    for (int mt = 0; mt < 2; mt++)
#pragma unroll
        for (int d = 0; d < 8; d++)
#pragma unroll
            for (int e = 0; e < 4; e++) o[mt][d][e] = 0.f;
    float mv[2][2], lv[2][2];
#pragma unroll
    for (int mt = 0; mt < 2; mt++) { mv[mt][0] = mv[mt][1] = -1e30f; lv[mt][0] = lv[mt][1] = 0.f; }

    const int rA = lane >> 2;
    const int wrow_min = q0 + w * 32;
    const int wrow_max = wrow_min + 31;

    for (int j = 0; j < ntiles; j++) {
        const int k0 = j * 64;
        if (j + 1 < ntiles) load_kv((j + 1) % 3, j + 1);
        if (j + 1 < ntiles) CPWAIT1(); else CPWAIT0();
        __syncthreads();

        if (k0 > wrow_max) continue;        // fully masked for this warp

        const uint32_t kvb = sb + AKV + (j % 3) * KVB;

        // ---- S = Q K^T  (log2-domain scale applied after) ----
        float s[2][8][4];
#pragma unroll
        for (int mt = 0; mt < 2; mt++)
#pragma unroll
            for (int ot = 0; ot < 8; ot++)
#pragma unroll
                for (int e = 0; e < 4; e++) s[mt][ot][e] = 0.f;
#pragma unroll
        for (int ks = 0; ks < 4; ks++) {
            uint32_t kh[4][4];
#pragma unroll
            for (int nt = 0; nt < 4; nt++) {
                uint32_t ro = (nt * 16 + (lane & 15)) * 128 + ks * 32 + (lane >> 4) * 16;
                ldsm4(kh[nt], kvb + SW128(ro));
            }
#pragma unroll
            for (int mt = 0; mt < 2; mt++)
#pragma unroll
                for (int nt = 0; nt < 4; nt++) {
                    mma16816(s[mt][2 * nt],     qh[ks][mt], kh[nt][0], kh[nt][2]);
                    mma16816(s[mt][2 * nt + 1], qh[ks][mt], kh[nt][1], kh[nt][3]);
                }
        }

        // ---- scale (log2 domain) + causal mask ----
        const bool need_mask = (k0 + 63 > wrow_min);
#pragma unroll
        for (int mt = 0; mt < 2; mt++)
#pragma unroll
            for (int ot = 0; ot < 8; ot++)
#pragma unroll
                for (int e = 0; e < 4; e++) {
                    float v = s[mt][ot][e] * QK_SCALE;
                    if (need_mask) {
                        int n = k0 + ot * 8 + (lane & 3) * 2 + (e & 1);
                        int r = wrow_min + mt * 16 + rA + ((e >= 2) ? 8 : 0);
                        if (n > r) v = -1e30f;
                    }
                    s[mt][ot][e] = v;
                }

        // ---- online softmax (base-2) ----
#pragma unroll
        for (int mt = 0; mt < 2; mt++) {
            float mx0 = -1e30f, mx1 = -1e30f;
#pragma unroll
            for (int ot = 0; ot < 8; ot++) {
                mx0 = fmaxf(mx0, fmaxf(s[mt][ot][0], s[mt][ot][1]));
                mx1 = fmaxf(mx1, fmaxf(s[mt][ot][2], s[mt][ot][3]));
            }
            mx0 = fmaxf(mx0, __shfl_xor_sync(0xffffffff, mx0, 1));
            mx0 = fmaxf(mx0, __shfl_xor_sync(0xffffffff, mx0, 2));
            mx1 = fmaxf(mx1, __shfl_xor_sync(0xffffffff, mx1, 1));
            mx1 = fmaxf(mx1, __shfl_xor_sync(0xffffffff, mx1, 2));

            float mn0 = fmaxf(mv[mt][0], mx0), mn1 = fmaxf(mv[mt][1], mx1);
            float a0 = exp2f(mv[mt][0] - mn0), a1 = exp2f(mv[mt][1] - mn1);
            mv[mt][0] = mn0; mv[mt][1] = mn1;
            lv[mt][0] *= a0; lv[mt][1] *= a1;
#pragma unroll
            for (int d = 0; d < 8; d++) {
                o[mt][d][0] *= a0; o[mt][d][1] *= a0;
                o[mt][d][2] *= a1; o[mt][d][3] *= a1;
            }
#pragma unroll
            for (int ot = 0; ot < 8; ot++) {
                float p0 = exp2f(s[mt][ot][0] - mn0);
                float p1 = exp2f(s[mt][ot][1] - mn0);
                float p2 = exp2f(s[mt][ot][2] - mn1);
                float p3 = exp2f(s[mt][ot][3] - mn1);
                lv[mt][0] += p0 + p1; lv[mt][1] += p2 + p3;
                s[mt][ot][0] = p0; s[mt][ot][1] = p1;
                s[mt][ot][2] = p2; s[mt][ot][3] = p3;
            }
        }

        // ---- O += P V  (V fragments shared across both m-tiles) ----
#pragma unroll
        for (int kt = 0; kt < 4; kt++) {
            uint32_t vh[4][4];
#pragma unroll
            for (int dt = 0; dt < 4; dt++) {
                uint32_t ro = (kt * 16 + (lane & 15)) * 128 + dt * 32 + (lane >> 4) * 16;
                ldsm4t(vh[dt], kvb + 8192 + SW128(ro));
            }
#pragma unroll
            for (int mt = 0; mt < 2; mt++) {
                uint32_t ap[4] = {
                    packh(s[mt][2 * kt][0],     s[mt][2 * kt][1]),
                    packh(s[mt][2 * kt][2],     s[mt][2 * kt][3]),
                    packh(s[mt][2 * kt + 1][0], s[mt][2 * kt + 1][1]),
                    packh(s[mt][2 * kt + 1][2], s[mt][2 * kt + 1][3])
                };
#pragma unroll
                for (int dt = 0; dt < 4; dt++) {
                    mma16816(o[mt][2 * dt],     ap, vh[dt][0], vh[dt][1]);
                    mma16816(o[mt][2 * dt + 1], ap, vh[dt][2], vh[dt][3]);
                }
            }
        }
    }

    // ---- finalize ----
#pragma unroll
    for (int mt = 0; mt < 2; mt++) {
        float l0 = lv[mt][0], l1 = lv[mt][1];
        l0 += __shfl_xor_sync(0xffffffff, l0, 1);
        l0 += __shfl_xor_sync(0xffffffff, l0, 2);
        l1 += __shfl_xor_sync(0xffffffff, l1, 1);
        l1 += __shfl_xor_sync(0xffffffff, l1, 2);
        const float i0 = 1.f / l0, i1 = 1.f / l1;

        const int row0 = q0 + w * 32 + mt * 16 + rA;
        const int cb   = h * 64 + (lane & 3) * 2;
#pragma unroll
        for (int d = 0; d < 8; d++) {
            int col = cb + d * 8;
            *(uint32_t*)&g_y[(size_t)row0 * C_DIM + col] =
                packh(o[mt][d][0] * i0, o[mt][d][1] * i0);
            *(uint32_t*)&g_y[(size_t)(row0 + 8) * C_DIM + col] =
                packh(o[mt][d][2] * i1, o[mt][d][3] * i1);
        }
    }
}

// ---------------------------------------------------------------------------
extern "C" void kernel_launch(void* const* d_in, const int* in_sizes, int n_in,
                              void* d_out, int out_size)
{
    const float* x      = (const float*)d_in[0];
    const float* w_attn = (const float*)d_in[1];
    const float* w_proj = (const float*)d_in[2];
    float* out = (float*)d_out;
    (void)in_sizes; (void)n_in; (void)out_size;

    cudaFuncSetAttribute(gemm_kernel<true>,
                         cudaFuncAttributeMaxDynamicSharedMemorySize, GEMM_SMEM);
    cudaFuncSetAttribute(gemm_kernel<false>,
                         cudaFuncAttributeMaxDynamicSharedMemorySize, GEMM_SMEM);
    cudaFuncSetAttribute(attn_kernel,
                         cudaFuncAttributeMaxDynamicSharedMemorySize, ATTN_SMEM);

    void *p_x, *p_wa, *p_wp, *p_qkv, *p_y;
    cudaGetSymbolAddress(&p_x, g_x);
    cudaGetSymbolAddress(&p_wa, g_wa);
    cudaGetSymbolAddress(&p_wp, g_wp);
    cudaGetSymbolAddress(&p_qkv, g_qkv);
    cudaGetSymbolAddress(&p_y, g_y);

    // 1) convert all inputs to fp16 (single launch)
    cvt_all_kernel<<<8192, 256>>>(x, w_attn, w_proj);

    // 2) qkv = x @ w_attn^T  -> fp16
    gemm_kernel<true><<<dim3(F_DIM / 256, T_SEQ / 128), 256, GEMM_SMEM>>>(
        (const __half*)p_x, (const __half*)p_wa,
        nullptr, (__half*)p_qkv, C_DIM, F_DIM);

    // 3) tensor-core causal attention -> fp16 y
    attn_kernel<<<dim3(T_SEQ / 128, H_NUM), 128, ATTN_SMEM>>>();

    // 4) out = y @ w_proj^T  (fp32 output)
    gemm_kernel<false><<<dim3(C_DIM / 256, T_SEQ / 128), 256, GEMM_SMEM>>>(
        (const __half*)p_y, (const __half*)p_wp,
        out, nullptr, C_DIM, C_DIM);
}

// round 14
// speedup vs baseline: 17.7959x; 1.1369x over previous
#include <cuda_runtime.h>
#include <cuda_fp16.h>
#include <cstdint>

#define T_SEQ  4096
#define C_DIM  1024
#define H_NUM  16
#define D_HEAD 64
#define F_DIM  3072

// ---------------------------------------------------------------------------
// Device globals (no allocations allowed)
// ---------------------------------------------------------------------------
__device__ __half g_x[T_SEQ * C_DIM];
__device__ __half g_wa[F_DIM * C_DIM];
__device__ __half g_wp[C_DIM * C_DIM];
__device__ __half g_qkv[(size_t)T_SEQ * F_DIM];
__device__ __half g_y[T_SEQ * C_DIM];

// ---------------------------------------------------------------------------
// Helpers
// ---------------------------------------------------------------------------
__device__ __forceinline__ uint32_t s2u(const void* p) {
    uint32_t a;
    asm("{ .reg .u64 t; cvta.to.shared.u64 t, %1; cvt.u32.u64 %0, t; }"
        : "=r"(a) : "l"(p));
    return a;
}
#define SW128(o) ((uint32_t)(o) ^ ((((uint32_t)(o)) >> 3) & 0x70))

__device__ __forceinline__ void ldsm4(uint32_t* r, uint32_t addr) {
    asm volatile("ldmatrix.sync.aligned.m8n8.x4.shared.b16 {%0,%1,%2,%3}, [%4];"
                 : "=r"(r[0]), "=r"(r[1]), "=r"(r[2]), "=r"(r[3]) : "r"(addr));
}
__device__ __forceinline__ void ldsm4t(uint32_t* r, uint32_t addr) {
    asm volatile("ldmatrix.sync.aligned.m8n8.x4.trans.shared.b16 {%0,%1,%2,%3}, [%4];"
                 : "=r"(r[0]), "=r"(r[1]), "=r"(r[2]), "=r"(r[3]) : "r"(addr));
}
__device__ __forceinline__ void mma16816(float* c, const uint32_t* a,
                                         uint32_t b0, uint32_t b1) {
    asm volatile("mma.sync.aligned.m16n8k16.row.col.f32.f16.f16.f32 "
                 "{%0,%1,%2,%3}, {%4,%5,%6,%7}, {%8,%9}, {%0,%1,%2,%3};"
                 : "+f"(c[0]), "+f"(c[1]), "+f"(c[2]), "+f"(c[3])
                 : "r"(a[0]), "r"(a[1]), "r"(a[2]), "r"(a[3]), "r"(b0), "r"(b1));
}
#define CP16(s, g)  asm volatile("cp.async.cg.shared.global [%0], [%1], 16;" :: "r"(s), "l"(g))
#define CPCOMMIT()  asm volatile("cp.async.commit_group;" ::: "memory")
#define CPWAIT1()   asm volatile("cp.async.wait_group 1;" ::: "memory")
#define CPWAIT0()   asm volatile("cp.async.wait_group 0;" ::: "memory")

__device__ __forceinline__ uint32_t packh(float a, float b) {
    __half2 t = __floats2half2_rn(a, b);
    return reinterpret_cast<uint32_t&>(t);
}
__device__ __forceinline__ uint32_t h2e2(float a, float b) {
    __half2 t = h2exp2(__floats2half2_rn(a, b));
    return reinterpret_cast<uint32_t&>(t);
}

// ---------------------------------------------------------------------------
// Fused fp32 -> fp16 convert for x, w_attn, w_proj in ONE launch.
// ---------------------------------------------------------------------------
__global__ __launch_bounds__(256)
void cvt_all_kernel(const float* __restrict__ x,
                    const float* __restrict__ wa,
                    const float* __restrict__ wp)
{
    int b = blockIdx.x;
    const float* in;
    __half* out;
    int i;
    if (b < 4096)      { in = x;  out = g_x;  i = b * 256 + threadIdx.x; }
    else if (b < 7168) { in = wa; out = g_wa; i = (b - 4096) * 256 + threadIdx.x; }
    else               { in = wp; out = g_wp; i = (b - 7168) * 256 + threadIdx.x; }
    float4 v = ((const float4*)in)[i];
    ((uint32_t*)out)[2 * i]     = packh(v.x, v.y);
    ((uint32_t*)out)[2 * i + 1] = packh(v.z, v.w);
}

// ---------------------------------------------------------------------------
// fp16 GEMM:  C[M,N] = sum_k A[m,k]*B[n,k].  BM=128, BN=256, BK=64.
// 256 threads (8 warps: 2 along M x 4 along N, warp tile 64x64).
// ---------------------------------------------------------------------------
#define OA 0
#define OB 16384
#define GST 49152
#define GEMM_SMEM (2 * GST + 1024)

template<bool HALF_OUT>
__global__ __launch_bounds__(256, 1)
void gemm_kernel(const __half* __restrict__ A,
                 const __half* __restrict__ B,
                 float* __restrict__ Cout,
                 __half* __restrict__ Ch,
                 int K, int N)
{
    extern __shared__ char smraw[];
    const uint32_t sb = (s2u(smraw) + 1023u) & ~1023u;
    const int tid  = threadIdx.x;
    const int lane = tid & 31;
    const int w    = tid >> 5;
    const int wm   = w & 1;
    const int wn   = w >> 1;
    const int m0   = blockIdx.y * 128;
    const int n0   = blockIdx.x * 256;

    auto load_stage = [&](int stage, int kt) {
        const uint32_t s0 = sb + stage * GST;
        const int kk = kt * 64;
#pragma unroll
        for (int it = 0; it < 4; it++) {
            int idx = tid + it * 256;
            int r = idx >> 3, q = idx & 7;
            uint32_t so = SW128(r * 128 + q * 16);
            CP16(s0 + OA + so, (const void*)(A + (size_t)(m0 + r) * K + kk + q * 8));
        }
#pragma unroll
        for (int it = 0; it < 8; it++) {
            int idx = tid + it * 256;
            int r = idx >> 3, q = idx & 7;
            uint32_t so = SW128(r * 128 + q * 16);
            CP16(s0 + OB + so, (const void*)(B + (size_t)(n0 + r) * K + kk + q * 8));
        }
        CPCOMMIT();
    };

    float c[4][8][4];
#pragma unroll
    for (int mt = 0; mt < 4; mt++)
#pragma unroll
        for (int o = 0; o < 8; o++)
#pragma unroll
            for (int e = 0; e < 4; e++) c[mt][o][e] = 0.f;

    const int nT = K / 64;
    load_stage(0, 0);
    load_stage(1, 1);

    for (int t = 0; t < nT; t++) {
        if (t + 1 < nT) CPWAIT1(); else CPWAIT0();
        __syncthreads();
        const uint32_t s0 = sb + (t & 1) * GST;

#pragma unroll
        for (int ks = 0; ks < 4; ks++) {
            const uint32_t kb = ks * 32 + (lane >> 4) * 16;
            uint32_t ah[4][4];
#pragma unroll
            for (int mt = 0; mt < 4; mt++) {
                uint32_t ro = (wm * 64 + mt * 16 + (lane & 15)) * 128 + kb;
                ldsm4(ah[mt], s0 + OA + SW128(ro));
            }
            uint32_t bh[4][4];
#pragma unroll
            for (int nt = 0; nt < 4; nt++) {
                uint32_t ro = (wn * 64 + nt * 16 + (lane & 15)) * 128 + kb;
                ldsm4(bh[nt], s0 + OB + SW128(ro));
            }
#pragma unroll
            for (int mt = 0; mt < 4; mt++)
#pragma unroll
                for (int nt = 0; nt < 4; nt++) {
                    mma16816(c[mt][2 * nt],     ah[mt], bh[nt][0], bh[nt][2]);
                    mma16816(c[mt][2 * nt + 1], ah[mt], bh[nt][1], bh[nt][3]);
                }
        }
        __syncthreads();
        if (t + 2 < nT) load_stage(t & 1, t + 2);
    }

    const int rbase = m0 + wm * 64 + (lane >> 2);
    const int cbase = n0 + wn * 64 + (lane & 3) * 2;
#pragma unroll
    for (int mt = 0; mt < 4; mt++) {
#pragma unroll
        for (int o = 0; o < 8; o++) {
            int col = cbase + o * 8;
            int r0 = rbase + mt * 16;
            int r1 = r0 + 8;
            if (HALF_OUT) {
                *(uint32_t*)&Ch[(size_t)r0 * N + col] = packh(c[mt][o][0], c[mt][o][1]);
                *(uint32_t*)&Ch[(size_t)r1 * N + col] = packh(c[mt][o][2], c[mt][o][3]);
            } else {
                *(float2*)&Cout[(size_t)r0 * N + col] = make_float2(c[mt][o][0], c[mt][o][1]);
                *(float2*)&Cout[(size_t)r1 * N + col] = make_float2(c[mt][o][2], c[mt][o][3]);
            }
        }
    }
}

// ---------------------------------------------------------------------------
// Causal flash attention, fp16, balanced persistent pairing.
// Grid: 256 CTAs (flat).  CTA pid: head = pid>>4, p = pid&15; processes
// q-tiles {31-p, p} (66 KV-tile iterations total — identical for all CTAs).
// Block: 128 threads (4 warps), warp owns 32 q-rows.  2 CTAs/SM.
// Softmax: base-2, exp via h2exp2 (f16x2 MUFU) producing packed fp16 P;
// row-sum l accumulated by MMA against an all-ones B fragment.
// ---------------------------------------------------------------------------
#define AQ  0
#define AKV 16384
#define KVB 16384
#define ATTN_SMEM (AKV + 3 * KVB + 1024)

// log2(e) / sqrt(64)
#define QK_SCALE 0.1803368801111244f

__global__ __launch_bounds__(128, 2)
void attn_kernel()
{
    extern __shared__ char smraw[];
    const uint32_t sb = (s2u(smraw) + 1023u) & ~1023u;
    const int pid  = blockIdx.x;
    const int h    = pid >> 4;
    const int pr   = pid & 15;
    const int tid  = threadIdx.x;
    const int w    = tid >> 5;
    const int lane = tid & 31;
    const int rA   = lane >> 2;
    const uint32_t one2 = 0x3C003C00u;      // half2(1, 1)

    auto load_kv = [&](int buf, int k0) {
        const uint32_t b0 = sb + AKV + buf * KVB;
#pragma unroll
        for (int it = 0; it < 8; it++) {
            int idx = tid + it * 128;       // 0..1023
            int arr = idx >> 9;             // 0:K 1:V
            int rem = idx & 511;
            int r = rem >> 3, q = rem & 7;
            uint32_t so = SW128(r * 128 + q * 16) + arr * 8192;
            size_t go = (size_t)(k0 + r) * F_DIM + (arr ? 2 * C_DIM : C_DIM) + h * 64 + q * 8;
            CP16(b0 + so, (const void*)(g_qkv + go));
        }
        CPCOMMIT();
    };

    for (int rep = 0; rep < 2; rep++) {
        const int qt = rep ? pr : (31 - pr);
        const int q0 = qt * 128;
        const int ntiles = 2 * qt + 2;

        __syncthreads();                    // protect smem reuse across reps
        load_kv(0, 0);

        // ---- stage Q tile (128 rows) ----
#pragma unroll
        for (int it = 0; it < 8; it++) {
            int idx = tid + it * 128;
            int r = idx >> 3, q = idx & 7;
            size_t go = (size_t)(q0 + r) * F_DIM + h * 64 + q * 8;
            uint32_t so = SW128(r * 128 + q * 16);
            uint4 vh = *(const uint4*)&g_qkv[go];
            asm volatile("st.shared.v4.b32 [%0],{%1,%2,%3,%4};"
                         :: "r"(sb + AQ + so), "r"(vh.x), "r"(vh.y), "r"(vh.z), "r"(vh.w));
        }
        __syncthreads();

        uint32_t qh[4][2][4];
#pragma unroll
        for (int ks = 0; ks < 4; ks++)
#pragma unroll
            for (int mt = 0; mt < 2; mt++) {
                uint32_t ro = (w * 32 + mt * 16 + (lane & 15)) * 128 + ks * 32 + (lane >> 4) * 16;
                ldsm4(qh[ks][mt], sb + AQ + SW128(ro));
            }

        float o[2][8][4];
        float lacc[2][4];
        float mv[2][2];
#pragma unroll
        for (int mt = 0; mt < 2; mt++) {
#pragma unroll
            for (int d = 0; d < 8; d++)
#pragma unroll
                for (int e = 0; e < 4; e++) o[mt][d][e] = 0.f;
#pragma unroll
            for (int e = 0; e < 4; e++) lacc[mt][e] = 0.f;
            mv[mt][0] = mv[mt][1] = -1e30f;
        }

        const int wrow_min = q0 + w * 32;
        const int wrow_max = wrow_min + 31;

        for (int j = 0; j < ntiles; j++) {
            const int k0 = j * 64;
            if (j + 1 < ntiles) load_kv((j + 1) % 3, (j + 1) * 64);
            if (j + 1 < ntiles) CPWAIT1(); else CPWAIT0();
            __syncthreads();

            if (k0 > wrow_max) continue;

            const uint32_t kvb = sb + AKV + (j % 3) * KVB;

            // ---- S = Q K^T ----
            float s[2][8][4];
#pragma unroll
            for (int mt = 0; mt < 2; mt++)
#pragma unroll
                for (int ot = 0; ot < 8; ot++)
#pragma unroll
                    for (int e = 0; e < 4; e++) s[mt][ot][e] = 0.f;
#pragma unroll
            for (int ks = 0; ks < 4; ks++) {
                uint32_t kh[4][4];
#pragma unroll
                for (int nt = 0; nt < 4; nt++) {
                    uint32_t ro = (nt * 16 + (lane & 15)) * 128 + ks * 32 + (lane >> 4) * 16;
                    ldsm4(kh[nt], kvb + SW128(ro));
                }
#pragma unroll
                for (int mt = 0; mt < 2; mt++)
#pragma unroll
                    for (int nt = 0; nt < 4; nt++) {
                        mma16816(s[mt][2 * nt],     qh[ks][mt], kh[nt][0], kh[nt][2]);
                        mma16816(s[mt][2 * nt + 1], qh[ks][mt], kh[nt][1], kh[nt][3]);
                    }
            }

            // ---- scale (log2 domain) + causal mask ----
            const bool need_mask = (k0 + 63 > wrow_min);
#pragma unroll
            for (int mt = 0; mt < 2; mt++)
#pragma unroll
                for (int ot = 0; ot < 8; ot++)
#pragma unroll
                    for (int e = 0; e < 4; e++) {
                        float v = s[mt][ot][e] * QK_SCALE;
                        if (need_mask) {
                            int n = k0 + ot * 8 + (lane & 3) * 2 + (e & 1);
                            int r = wrow_min + mt * 16 + rA + ((e >= 2) ? 8 : 0);
                            if (n > r) v = -1e30f;
                        }
                        s[mt][ot][e] = v;
                    }

            // ---- online softmax (base-2, fp16 exp -> packed P) ----
            uint32_t p01[2][8], p23[2][8];
#pragma unroll
            for (int mt = 0; mt < 2; mt++) {
                float mx0 = -1e30f, mx1 = -1e30f;
#pragma unroll
                for (int ot = 0; ot < 8; ot++) {
                    mx0 = fmaxf(mx0, fmaxf(s[mt][ot][0], s[mt][ot][1]));
                    mx1 = fmaxf(mx1, fmaxf(s[mt][ot][2], s[mt][ot][3]));
                }
                mx0 = fmaxf(mx0, __shfl_xor_sync(0xffffffff, mx0, 1));
                mx0 = fmaxf(mx0, __shfl_xor_sync(0xffffffff, mx0, 2));
                mx1 = fmaxf(mx1, __shfl_xor_sync(0xffffffff, mx1, 1));
                mx1 = fmaxf(mx1, __shfl_xor_sync(0xffffffff, mx1, 2));

                float mn0 = fmaxf(mv[mt][0], mx0), mn1 = fmaxf(mv[mt][1], mx1);
                float a0 = exp2f(mv[mt][0] - mn0), a1 = exp2f(mv[mt][1] - mn1);
                mv[mt][0] = mn0; mv[mt][1] = mn1;
                lacc[mt][0] *= a0; lacc[mt][1] *= a0;
                lacc[mt][2] *= a1; lacc[mt][3] *= a1;
#pragma unroll
                for (int d = 0; d < 8; d++) {
                    o[mt][d][0] *= a0; o[mt][d][1] *= a0;
                    o[mt][d][2] *= a1; o[mt][d][3] *= a1;
                }
#pragma unroll
                for (int ot = 0; ot < 8; ot++) {
                    p01[mt][ot] = h2e2(s[mt][ot][0] - mn0, s[mt][ot][1] - mn0);
                    p23[mt][ot] = h2e2(s[mt][ot][2] - mn1, s[mt][ot][3] - mn1);
                }
            }

            // ---- O += P V,  l += P·1 ----
#pragma unroll
            for (int kt = 0; kt < 4; kt++) {
                uint32_t vh[4][4];
#pragma unroll
                for (int dt = 0; dt < 4; dt++) {
                    uint32_t ro = (kt * 16 + (lane & 15)) * 128 + dt * 32 + (lane >> 4) * 16;
                    ldsm4t(vh[dt], kvb + 8192 + SW128(ro));
                }
#pragma unroll
                for (int mt = 0; mt < 2; mt++) {
                    uint32_t ap[4] = { p01[mt][2 * kt], p23[mt][2 * kt],
                                       p01[mt][2 * kt + 1], p23[mt][2 * kt + 1] };
                    mma16816(lacc[mt], ap, one2, one2);
#pragma unroll
                    for (int dt = 0; dt < 4; dt++) {
                        mma16816(o[mt][2 * dt],     ap, vh[dt][0], vh[dt][1]);
                        mma16816(o[mt][2 * dt + 1], ap, vh[dt][2], vh[dt][3]);
                    }
                }
            }
        }

        // ---- finalize (l already fully reduced by the MMA contraction) ----
#pragma unroll
        for (int mt = 0; mt < 2; mt++) {
            const float i0 = 1.f / lacc[mt][0], i1 = 1.f / lacc[mt][2];
            const int row0 = q0 + w * 32 + mt * 16 + rA;
            const int cb   = h * 64 + (lane & 3) * 2;
#pragma unroll
            for (int d = 0; d < 8; d++) {
                int col = cb + d * 8;
                *(uint32_t*)&g_y[(size_t)row0 * C_DIM + col] =
                    packh(o[mt][d][0] * i0, o[mt][d][1] * i0);
                *(uint32_t*)&g_y[(size_t)(row0 + 8) * C_DIM + col] =
                    packh(o[mt][d][2] * i1, o[mt][d][3] * i1);
            }
        }
    }
}

// ---------------------------------------------------------------------------
extern "C" void kernel_launch(void* const* d_in, const int* in_sizes, int n_in,
                              void* d_out, int out_size)
{
    const float* x      = (const float*)d_in[0];
    const float* w_attn = (const float*)d_in[1];
    const float* w_proj = (const float*)d_in[2];
    float* out = (float*)d_out;
    (void)in_sizes; (void)n_in; (void)out_size;

    cudaFuncSetAttribute(gemm_kernel<true>,
                         cudaFuncAttributeMaxDynamicSharedMemorySize, GEMM_SMEM);
    cudaFuncSetAttribute(gemm_kernel<false>,
                         cudaFuncAttributeMaxDynamicSharedMemorySize, GEMM_SMEM);
    cudaFuncSetAttribute(attn_kernel,
                         cudaFuncAttributeMaxDynamicSharedMemorySize, ATTN_SMEM);

    void *p_x, *p_wa, *p_wp, *p_qkv, *p_y;
    cudaGetSymbolAddress(&p_x, g_x);
    cudaGetSymbolAddress(&p_wa, g_wa);
    cudaGetSymbolAddress(&p_wp, g_wp);
    cudaGetSymbolAddress(&p_qkv, g_qkv);
    cudaGetSymbolAddress(&p_y, g_y);

    // 1) convert all inputs to fp16 (single launch)
    cvt_all_kernel<<<8192, 256>>>(x, w_attn, w_proj);

    // 2) qkv = x @ w_attn^T  -> fp16
    gemm_kernel<true><<<dim3(F_DIM / 256, T_SEQ / 128), 256, GEMM_SMEM>>>(
        (const __half*)p_x, (const __half*)p_wa,
        nullptr, (__half*)p_qkv, C_DIM, F_DIM);

    // 3) balanced persistent causal attention -> fp16 y
    attn_kernel<<<256, 128, ATTN_SMEM>>>();

    // 4) out = y @ w_proj^T  (fp32 output)
    gemm_kernel<false><<<dim3(C_DIM / 256, T_SEQ / 128), 256, GEMM_SMEM>>>(
        (const __half*)p_y, (const __half*)p_wp,
        out, nullptr, C_DIM, C_DIM);
}

// round 15
// speedup vs baseline: 18.6765x; 1.0495x over previous
#include <cuda_runtime.h>
#include <cuda_fp16.h>
#include <cstdint>

#define T_SEQ  4096
#define C_DIM  1024
#define H_NUM  16
#define D_HEAD 64
#define F_DIM  3072

// ---------------------------------------------------------------------------
// Device globals (no allocations allowed)
// ---------------------------------------------------------------------------
__device__ __half g_x[T_SEQ * C_DIM];
__device__ __half g_wa[F_DIM * C_DIM];
__device__ __half g_wp[C_DIM * C_DIM];
__device__ __half g_qkv[(size_t)T_SEQ * F_DIM];
__device__ __half g_y[T_SEQ * C_DIM];

// ---------------------------------------------------------------------------
// Helpers
// ---------------------------------------------------------------------------
__device__ __forceinline__ uint32_t s2u(const void* p) {
    uint32_t a;
    asm("{ .reg .u64 t; cvta.to.shared.u64 t, %1; cvt.u32.u64 %0, t; }"
        : "=r"(a) : "l"(p));
    return a;
}
#define SW128(o) ((uint32_t)(o) ^ ((((uint32_t)(o)) >> 3) & 0x70))

__device__ __forceinline__ void ldsm4(uint32_t* r, uint32_t addr) {
    asm volatile("ldmatrix.sync.aligned.m8n8.x4.shared.b16 {%0,%1,%2,%3}, [%4];"
                 : "=r"(r[0]), "=r"(r[1]), "=r"(r[2]), "=r"(r[3]) : "r"(addr));
}
__device__ __forceinline__ void ldsm4t(uint32_t* r, uint32_t addr) {
    asm volatile("ldmatrix.sync.aligned.m8n8.x4.trans.shared.b16 {%0,%1,%2,%3}, [%4];"
                 : "=r"(r[0]), "=r"(r[1]), "=r"(r[2]), "=r"(r[3]) : "r"(addr));
}
__device__ __forceinline__ void mma16816(float* c, const uint32_t* a,
                                         uint32_t b0, uint32_t b1) {
    asm volatile("mma.sync.aligned.m16n8k16.row.col.f32.f16.f16.f32 "
                 "{%0,%1,%2,%3}, {%4,%5,%6,%7}, {%8,%9}, {%0,%1,%2,%3};"
                 : "+f"(c[0]), "+f"(c[1]), "+f"(c[2]), "+f"(c[3])
                 : "r"(a[0]), "r"(a[1]), "r"(a[2]), "r"(a[3]), "r"(b0), "r"(b1));
}
#define CP16(s, g)  asm volatile("cp.async.cg.shared.global [%0], [%1], 16;" :: "r"(s), "l"(g))
#define CPCOMMIT()  asm volatile("cp.async.commit_group;" ::: "memory")
#define CPWAIT1()   asm volatile("cp.async.wait_group 1;" ::: "memory")
#define CPWAIT0()   asm volatile("cp.async.wait_group 0;" ::: "memory")

__device__ __forceinline__ uint32_t packh(float a, float b) {
    __half2 t = __floats2half2_rn(a, b);
    return reinterpret_cast<uint32_t&>(t);
}
__device__ __forceinline__ uint32_t h2e2(float a, float b) {
    __half2 t = h2exp2(__floats2half2_rn(a, b));
    return reinterpret_cast<uint32_t&>(t);
}

// ---------------------------------------------------------------------------
// Fused fp32 -> fp16 convert for x, w_attn, w_proj in ONE launch.
// ---------------------------------------------------------------------------
__global__ __launch_bounds__(256)
void cvt_all_kernel(const float* __restrict__ x,
                    const float* __restrict__ wa,
                    const float* __restrict__ wp)
{
    int b = blockIdx.x;
    const float* in;
    __half* out;
    int i;
    if (b < 4096)      { in = x;  out = g_x;  i = b * 256 + threadIdx.x; }
    else if (b < 7168) { in = wa; out = g_wa; i = (b - 4096) * 256 + threadIdx.x; }
    else               { in = wp; out = g_wp; i = (b - 7168) * 256 + threadIdx.x; }
    float4 v = ((const float4*)in)[i];
    ((uint32_t*)out)[2 * i]     = packh(v.x, v.y);
    ((uint32_t*)out)[2 * i + 1] = packh(v.z, v.w);
}

// ---------------------------------------------------------------------------
// fp16 GEMM:  C[M,N] = sum_k A[m,k]*B[n,k].  BM=128, BN=256, BK=64.
// 256 threads (8 warps: 2 along M x 4 along N, warp tile 64x64).
// ---------------------------------------------------------------------------
#define OA 0
#define OB 16384
#define GST 49152
#define GEMM_SMEM (2 * GST + 1024)

template<bool HALF_OUT>
__global__ __launch_bounds__(256, 1)
void gemm_kernel(const __half* __restrict__ A,
                 const __half* __restrict__ B,
                 float* __restrict__ Cout,
                 __half* __restrict__ Ch,
                 int K, int N)
{
    extern __shared__ char smraw[];
    const uint32_t sb = (s2u(smraw) + 1023u) & ~1023u;
    const int tid  = threadIdx.x;
    const int lane = tid & 31;
    const int w    = tid >> 5;
    const int wm   = w & 1;
    const int wn   = w >> 1;
    const int m0   = blockIdx.y * 128;
    const int n0   = blockIdx.x * 256;

    auto load_stage = [&](int stage, int kt) {
        const uint32_t s0 = sb + stage * GST;
        const int kk = kt * 64;
#pragma unroll
        for (int it = 0; it < 4; it++) {
            int idx = tid + it * 256;
            int r = idx >> 3, q = idx & 7;
            uint32_t so = SW128(r * 128 + q * 16);
            CP16(s0 + OA + so, (const void*)(A + (size_t)(m0 + r) * K + kk + q * 8));
        }
#pragma unroll
        for (int it = 0; it < 8; it++) {
            int idx = tid + it * 256;
            int r = idx >> 3, q = idx & 7;
            uint32_t so = SW128(r * 128 + q * 16);
            CP16(s0 + OB + so, (const void*)(B + (size_t)(n0 + r) * K + kk + q * 8));
        }
        CPCOMMIT();
    };

    float c[4][8][4];
#pragma unroll
    for (int mt = 0; mt < 4; mt++)
#pragma unroll
        for (int o = 0; o < 8; o++)
#pragma unroll
            for (int e = 0; e < 4; e++) c[mt][o][e] = 0.f;

    const int nT = K / 64;
    load_stage(0, 0);
    load_stage(1, 1);

    for (int t = 0; t < nT; t++) {
        if (t + 1 < nT) CPWAIT1(); else CPWAIT0();
        __syncthreads();
        const uint32_t s0 = sb + (t & 1) * GST;

#pragma unroll
        for (int ks = 0; ks < 4; ks++) {
            const uint32_t kb = ks * 32 + (lane >> 4) * 16;
            uint32_t ah[4][4];
#pragma unroll
            for (int mt = 0; mt < 4; mt++) {
                uint32_t ro = (wm * 64 + mt * 16 + (lane & 15)) * 128 + kb;
                ldsm4(ah[mt], s0 + OA + SW128(ro));
            }
            uint32_t bh[4][4];
#pragma unroll
            for (int nt = 0; nt < 4; nt++) {
                uint32_t ro = (wn * 64 + nt * 16 + (lane & 15)) * 128 + kb;
                ldsm4(bh[nt], s0 + OB + SW128(ro));
            }
#pragma unroll
            for (int mt = 0; mt < 4; mt++)
#pragma unroll
                for (int nt = 0; nt < 4; nt++) {
                    mma16816(c[mt][2 * nt],     ah[mt], bh[nt][0], bh[nt][2]);
                    mma16816(c[mt][2 * nt + 1], ah[mt], bh[nt][1], bh[nt][3]);
                }
        }
        __syncthreads();
        if (t + 2 < nT) load_stage(t & 1, t + 2);
    }

    const int rbase = m0 + wm * 64 + (lane >> 2);
    const int cbase = n0 + wn * 64 + (lane & 3) * 2;
#pragma unroll
    for (int mt = 0; mt < 4; mt++) {
#pragma unroll
        for (int o = 0; o < 8; o++) {
            int col = cbase + o * 8;
            int r0 = rbase + mt * 16;
            int r1 = r0 + 8;
            if (HALF_OUT) {
                *(uint32_t*)&Ch[(size_t)r0 * N + col] = packh(c[mt][o][0], c[mt][o][1]);
                *(uint32_t*)&Ch[(size_t)r1 * N + col] = packh(c[mt][o][2], c[mt][o][3]);
            } else {
                *(float2*)&Cout[(size_t)r0 * N + col] = make_float2(c[mt][o][0], c[mt][o][1]);
                *(float2*)&Cout[(size_t)r1 * N + col] = make_float2(c[mt][o][2], c[mt][o][3]);
            }
        }
    }
}

// ---------------------------------------------------------------------------
// Causal flash attention, fp16, balanced persistent pairing, FIXED-MAX
// softmax:  p = 2^(s*scale - 8)  — no running max, no O rescale.
// Both O and l are uniformly scaled by 2^-8; the ratio O/l is exact.
// Grid: 256 CTAs; CTA processes q-tiles {31-p, p} (66 KV-tiles each).
// Block: 128 threads (4 warps), warp owns 32 q-rows.  2 CTAs/SM.
// l accumulated via MMA against an all-ones B fragment.
// ---------------------------------------------------------------------------
#define AQ  0
#define AKV 16384
#define KVB 16384
#define ATTN_SMEM (AKV + 3 * KVB + 1024)

// log2(e) / sqrt(64)
#define QK_SCALE 0.1803368801111244f
#define M_BIAS   8.0f

__global__ __launch_bounds__(128, 2)
void attn_kernel()
{
    extern __shared__ char smraw[];
    const uint32_t sb = (s2u(smraw) + 1023u) & ~1023u;
    const int pid  = blockIdx.x;
    const int h    = pid >> 4;
    const int pr   = pid & 15;
    const int tid  = threadIdx.x;
    const int w    = tid >> 5;
    const int lane = tid & 31;
    const int rA   = lane >> 2;
    const uint32_t one2 = 0x3C003C00u;      // half2(1, 1)

    auto load_kv = [&](int buf, int k0) {
        const uint32_t b0 = sb + AKV + buf * KVB;
#pragma unroll
        for (int it = 0; it < 8; it++) {
            int idx = tid + it * 128;       // 0..1023
            int arr = idx >> 9;             // 0:K 1:V
            int rem = idx & 511;
            int r = rem >> 3, q = rem & 7;
            uint32_t so = SW128(r * 128 + q * 16) + arr * 8192;
            size_t go = (size_t)(k0 + r) * F_DIM + (arr ? 2 * C_DIM : C_DIM) + h * 64 + q * 8;
            CP16(b0 + so, (const void*)(g_qkv + go));
        }
        CPCOMMIT();
    };

    for (int rep = 0; rep < 2; rep++) {
        const int qt = rep ? pr : (31 - pr);
        const int q0 = qt * 128;
        const int ntiles = 2 * qt + 2;

        __syncthreads();                    // protect smem reuse across reps
        load_kv(0, 0);

        // ---- stage Q tile (128 rows) ----
#pragma unroll
        for (int it = 0; it < 8; it++) {
            int idx = tid + it * 128;
            int r = idx >> 3, q = idx & 7;
            size_t go = (size_t)(q0 + r) * F_DIM + h * 64 + q * 8;
            uint32_t so = SW128(r * 128 + q * 16);
            uint4 vh = *(const uint4*)&g_qkv[go];
            asm volatile("st.shared.v4.b32 [%0],{%1,%2,%3,%4};"
                         :: "r"(sb + AQ + so), "r"(vh.x), "r"(vh.y), "r"(vh.z), "r"(vh.w));
        }
        __syncthreads();

        uint32_t qh[4][2][4];
#pragma unroll
        for (int ks = 0; ks < 4; ks++)
#pragma unroll
            for (int mt = 0; mt < 2; mt++) {
                uint32_t ro = (w * 32 + mt * 16 + (lane & 15)) * 128 + ks * 32 + (lane >> 4) * 16;
                ldsm4(qh[ks][mt], sb + AQ + SW128(ro));
            }

        float o[2][8][4];
        float lacc[2][4];
#pragma unroll
        for (int mt = 0; mt < 2; mt++) {
#pragma unroll
            for (int d = 0; d < 8; d++)
#pragma unroll
                for (int e = 0; e < 4; e++) o[mt][d][e] = 0.f;
#pragma unroll
            for (int e = 0; e < 4; e++) lacc[mt][e] = 0.f;
        }

        const int wrow_min = q0 + w * 32;
        const int wrow_max = wrow_min + 31;

        for (int j = 0; j < ntiles; j++) {
            const int k0 = j * 64;
            if (j + 1 < ntiles) load_kv((j + 1) % 3, (j + 1) * 64);
            if (j + 1 < ntiles) CPWAIT1(); else CPWAIT0();
            __syncthreads();

            if (k0 > wrow_max) continue;

            const uint32_t kvb = sb + AKV + (j % 3) * KVB;

            // ---- S = Q K^T ----
            float s[2][8][4];
#pragma unroll
            for (int mt = 0; mt < 2; mt++)
#pragma unroll
                for (int ot = 0; ot < 8; ot++)
#pragma unroll
                    for (int e = 0; e < 4; e++) s[mt][ot][e] = 0.f;
#pragma unroll
            for (int ks = 0; ks < 4; ks++) {
                uint32_t kh[4][4];
#pragma unroll
                for (int nt = 0; nt < 4; nt++) {
                    uint32_t ro = (nt * 16 + (lane & 15)) * 128 + ks * 32 + (lane >> 4) * 16;
                    ldsm4(kh[nt], kvb + SW128(ro));
                }
#pragma unroll
                for (int mt = 0; mt < 2; mt++)
#pragma unroll
                    for (int nt = 0; nt < 4; nt++) {
                        mma16816(s[mt][2 * nt],     qh[ks][mt], kh[nt][0], kh[nt][2]);
                        mma16816(s[mt][2 * nt + 1], qh[ks][mt], kh[nt][1], kh[nt][3]);
                    }
            }

            // ---- fixed-max softmax: p = 2^(s*scale - 8), mask -> 0 ----
            const bool need_mask = (k0 + 63 > wrow_min);
            uint32_t p01[2][8], p23[2][8];
#pragma unroll
            for (int mt = 0; mt < 2; mt++) {
#pragma unroll
                for (int ot = 0; ot < 8; ot++) {
                    float v0 = fmaf(s[mt][ot][0], QK_SCALE, -M_BIAS);
                    float v1 = fmaf(s[mt][ot][1], QK_SCALE, -M_BIAS);
                    float v2 = fmaf(s[mt][ot][2], QK_SCALE, -M_BIAS);
                    float v3 = fmaf(s[mt][ot][3], QK_SCALE, -M_BIAS);
                    if (need_mask) {
                        int n = k0 + ot * 8 + (lane & 3) * 2;
                        int r0 = wrow_min + mt * 16 + rA;
                        int r1 = r0 + 8;
                        if (n > r0)     v0 = -1e30f;
                        if (n + 1 > r0) v1 = -1e30f;
                        if (n > r1)     v2 = -1e30f;
                        if (n + 1 > r1) v3 = -1e30f;
                    }
                    p01[mt][ot] = h2e2(v0, v1);
                    p23[mt][ot] = h2e2(v2, v3);
                }
            }

            // ---- O += P V,  l += P·1 ----
#pragma unroll
            for (int kt = 0; kt < 4; kt++) {
                uint32_t vh[4][4];
#pragma unroll
                for (int dt = 0; dt < 4; dt++) {
                    uint32_t ro = (kt * 16 + (lane & 15)) * 128 + dt * 32 + (lane >> 4) * 16;
                    ldsm4t(vh[dt], kvb + 8192 + SW128(ro));
                }
#pragma unroll
                for (int mt = 0; mt < 2; mt++) {
                    uint32_t ap[4] = { p01[mt][2 * kt], p23[mt][2 * kt],
                                       p01[mt][2 * kt + 1], p23[mt][2 * kt + 1] };
                    mma16816(lacc[mt], ap, one2, one2);
#pragma unroll
                    for (int dt = 0; dt < 4; dt++) {
                        mma16816(o[mt][2 * dt],     ap, vh[dt][0], vh[dt][1]);
                        mma16816(o[mt][2 * dt + 1], ap, vh[dt][2], vh[dt][3]);
                    }
                }
            }
        }

        // ---- finalize (l fully reduced by the MMA contraction) ----
#pragma unroll
        for (int mt = 0; mt < 2; mt++) {
            const float i0 = 1.f / lacc[mt][0], i1 = 1.f / lacc[mt][2];
            const int row0 = q0 + w * 32 + mt * 16 + rA;
            const int cb   = h * 64 + (lane & 3) * 2;
#pragma unroll
            for (int d = 0; d < 8; d++) {
                int col = cb + d * 8;
                *(uint32_t*)&g_y[(size_t)row0 * C_DIM + col] =
                    packh(o[mt][d][0] * i0, o[mt][d][1] * i0);
                *(uint32_t*)&g_y[(size_t)(row0 + 8) * C_DIM + col] =
                    packh(o[mt][d][2] * i1, o[mt][d][3] * i1);
            }
        }
    }
}

// ---------------------------------------------------------------------------
extern "C" void kernel_launch(void* const* d_in, const int* in_sizes, int n_in,
                              void* d_out, int out_size)
{
    const float* x      = (const float*)d_in[0];
    const float* w_attn = (const float*)d_in[1];
    const float* w_proj = (const float*)d_in[2];
    float* out = (float*)d_out;
    (void)in_sizes; (void)n_in; (void)out_size;

    cudaFuncSetAttribute(gemm_kernel<true>,
                         cudaFuncAttributeMaxDynamicSharedMemorySize, GEMM_SMEM);
    cudaFuncSetAttribute(gemm_kernel<false>,
                         cudaFuncAttributeMaxDynamicSharedMemorySize, GEMM_SMEM);
    cudaFuncSetAttribute(attn_kernel,
                         cudaFuncAttributeMaxDynamicSharedMemorySize, ATTN_SMEM);

    void *p_x, *p_wa, *p_wp, *p_qkv, *p_y;
    cudaGetSymbolAddress(&p_x, g_x);
    cudaGetSymbolAddress(&p_wa, g_wa);
    cudaGetSymbolAddress(&p_wp, g_wp);
    cudaGetSymbolAddress(&p_qkv, g_qkv);
    cudaGetSymbolAddress(&p_y, g_y);

    // 1) convert all inputs to fp16 (single launch)
    cvt_all_kernel<<<8192, 256>>>(x, w_attn, w_proj);

    // 2) qkv = x @ w_attn^T  -> fp16
    gemm_kernel<true><<<dim3(F_DIM / 256, T_SEQ / 128), 256, GEMM_SMEM>>>(
        (const __half*)p_x, (const __half*)p_wa,
        nullptr, (__half*)p_qkv, C_DIM, F_DIM);

    // 3) balanced persistent causal attention -> fp16 y
    attn_kernel<<<256, 128, ATTN_SMEM>>>();

    // 4) out = y @ w_proj^T  (fp32 output)
    gemm_kernel<false><<<dim3(C_DIM / 256, T_SEQ / 128), 256, GEMM_SMEM>>>(
        (const __half*)p_y, (const __half*)p_wp,
        out, nullptr, C_DIM, C_DIM);
}

// round 16
// speedup vs baseline: 19.3187x; 1.0344x over previous
#include <cuda_runtime.h>
#include <cuda_fp16.h>
#include <cstdint>

#define T_SEQ  4096
#define C_DIM  1024
#define H_NUM  16
#define D_HEAD 64
#define F_DIM  3072

// ---------------------------------------------------------------------------
// Device globals (no allocations allowed)
// ---------------------------------------------------------------------------
__device__ __half g_x[T_SEQ * C_DIM];
__device__ __half g_wa[F_DIM * C_DIM];
__device__ __half g_wp[C_DIM * C_DIM];
__device__ __half g_qkv[(size_t)T_SEQ * F_DIM];
__device__ __half g_y[T_SEQ * C_DIM];
__device__ int    g_task_ctr;          // attention work-queue counter

// ---------------------------------------------------------------------------
// Helpers
// ---------------------------------------------------------------------------
__device__ __forceinline__ uint32_t s2u(const void* p) {
    uint32_t a;
    asm("{ .reg .u64 t; cvta.to.shared.u64 t, %1; cvt.u32.u64 %0, t; }"
        : "=r"(a) : "l"(p));
    return a;
}
#define SW128(o) ((uint32_t)(o) ^ ((((uint32_t)(o)) >> 3) & 0x70))

__device__ __forceinline__ void ldsm4(uint32_t* r, uint32_t addr) {
    asm volatile("ldmatrix.sync.aligned.m8n8.x4.shared.b16 {%0,%1,%2,%3}, [%4];"
                 : "=r"(r[0]), "=r"(r[1]), "=r"(r[2]), "=r"(r[3]) : "r"(addr));
}
__device__ __forceinline__ void ldsm4t(uint32_t* r, uint32_t addr) {
    asm volatile("ldmatrix.sync.aligned.m8n8.x4.trans.shared.b16 {%0,%1,%2,%3}, [%4];"
                 : "=r"(r[0]), "=r"(r[1]), "=r"(r[2]), "=r"(r[3]) : "r"(addr));
}
__device__ __forceinline__ void mma16816(float* c, const uint32_t* a,
                                         uint32_t b0, uint32_t b1) {
    asm volatile("mma.sync.aligned.m16n8k16.row.col.f32.f16.f16.f32 "
                 "{%0,%1,%2,%3}, {%4,%5,%6,%7}, {%8,%9}, {%0,%1,%2,%3};"
                 : "+f"(c[0]), "+f"(c[1]), "+f"(c[2]), "+f"(c[3])
                 : "r"(a[0]), "r"(a[1]), "r"(a[2]), "r"(a[3]), "r"(b0), "r"(b1));
}
#define CP16(s, g)  asm volatile("cp.async.cg.shared.global [%0], [%1], 16;" :: "r"(s), "l"(g))
#define CPCOMMIT()  asm volatile("cp.async.commit_group;" ::: "memory")
#define CPWAIT1()   asm volatile("cp.async.wait_group 1;" ::: "memory")
#define CPWAIT0()   asm volatile("cp.async.wait_group 0;" ::: "memory")

__device__ __forceinline__ uint32_t packh(float a, float b) {
    __half2 t = __floats2half2_rn(a, b);
    return reinterpret_cast<uint32_t&>(t);
}
__device__ __forceinline__ uint32_t h2e2(float a, float b) {
    __half2 t = h2exp2(__floats2half2_rn(a, b));
    return reinterpret_cast<uint32_t&>(t);
}

// ---------------------------------------------------------------------------
// Fused fp32 -> fp16 convert for x, w_attn, w_proj in ONE launch.
// Also resets the attention work-queue counter (graph-replay safe).
// ---------------------------------------------------------------------------
__global__ __launch_bounds__(256)
void cvt_all_kernel(const float* __restrict__ x,
                    const float* __restrict__ wa,
                    const float* __restrict__ wp)
{
    int b = blockIdx.x;
    if (b == 0 && threadIdx.x == 0) g_task_ctr = 0;
    const float* in;
    __half* out;
    int i;
    if (b < 4096)      { in = x;  out = g_x;  i = b * 256 + threadIdx.x; }
    else if (b < 7168) { in = wa; out = g_wa; i = (b - 4096) * 256 + threadIdx.x; }
    else               { in = wp; out = g_wp; i = (b - 7168) * 256 + threadIdx.x; }
    float4 v = ((const float4*)in)[i];
    ((uint32_t*)out)[2 * i]     = packh(v.x, v.y);
    ((uint32_t*)out)[2 * i + 1] = packh(v.z, v.w);
}

// ---------------------------------------------------------------------------
// fp16 GEMM:  C[M,N] = sum_k A[m,k]*B[n,k].  BM=128, BN=256, BK=64.
// 256 threads (8 warps: 2 along M x 4 along N, warp tile 64x64).
// ---------------------------------------------------------------------------
#define OA 0
#define OB 16384
#define GST 49152
#define GEMM_SMEM (2 * GST + 1024)

template<bool HALF_OUT>
__global__ __launch_bounds__(256, 1)
void gemm_kernel(const __half* __restrict__ A,
                 const __half* __restrict__ B,
                 float* __restrict__ Cout,
                 __half* __restrict__ Ch,
                 int K, int N)
{
    extern __shared__ char smraw[];
    const uint32_t sb = (s2u(smraw) + 1023u) & ~1023u;
    const int tid  = threadIdx.x;
    const int lane = tid & 31;
    const int w    = tid >> 5;
    const int wm   = w & 1;
    const int wn   = w >> 1;
    const int m0   = blockIdx.y * 128;
    const int n0   = blockIdx.x * 256;

    auto load_stage = [&](int stage, int kt) {
        const uint32_t s0 = sb + stage * GST;
        const int kk = kt * 64;
#pragma unroll
        for (int it = 0; it < 4; it++) {
            int idx = tid + it * 256;
            int r = idx >> 3, q = idx & 7;
            uint32_t so = SW128(r * 128 + q * 16);
            CP16(s0 + OA + so, (const void*)(A + (size_t)(m0 + r) * K + kk + q * 8));
        }
#pragma unroll
        for (int it = 0; it < 8; it++) {
            int idx = tid + it * 256;
            int r = idx >> 3, q = idx & 7;
            uint32_t so = SW128(r * 128 + q * 16);
            CP16(s0 + OB + so, (const void*)(B + (size_t)(n0 + r) * K + kk + q * 8));
        }
        CPCOMMIT();
    };

    float c[4][8][4];
#pragma unroll
    for (int mt = 0; mt < 4; mt++)
#pragma unroll
        for (int o = 0; o < 8; o++)
#pragma unroll
            for (int e = 0; e < 4; e++) c[mt][o][e] = 0.f;

    const int nT = K / 64;
    load_stage(0, 0);
    load_stage(1, 1);

    for (int t = 0; t < nT; t++) {
        if (t + 1 < nT) CPWAIT1(); else CPWAIT0();
        __syncthreads();
        const uint32_t s0 = sb + (t & 1) * GST;

#pragma unroll
        for (int ks = 0; ks < 4; ks++) {
            const uint32_t kb = ks * 32 + (lane >> 4) * 16;
            uint32_t ah[4][4];
#pragma unroll
            for (int mt = 0; mt < 4; mt++) {
                uint32_t ro = (wm * 64 + mt * 16 + (lane & 15)) * 128 + kb;
                ldsm4(ah[mt], s0 + OA + SW128(ro));
            }
            uint32_t bh[4][4];
#pragma unroll
            for (int nt = 0; nt < 4; nt++) {
                uint32_t ro = (wn * 64 + nt * 16 + (lane & 15)) * 128 + kb;
                ldsm4(bh[nt], s0 + OB + SW128(ro));
            }
#pragma unroll
            for (int mt = 0; mt < 4; mt++)
#pragma unroll
                for (int nt = 0; nt < 4; nt++) {
                    mma16816(c[mt][2 * nt],     ah[mt], bh[nt][0], bh[nt][2]);
                    mma16816(c[mt][2 * nt + 1], ah[mt], bh[nt][1], bh[nt][3]);
                }
        }
        __syncthreads();
        if (t + 2 < nT) load_stage(t & 1, t + 2);
    }

    const int rbase = m0 + wm * 64 + (lane >> 2);
    const int cbase = n0 + wn * 64 + (lane & 3) * 2;
#pragma unroll
    for (int mt = 0; mt < 4; mt++) {
#pragma unroll
        for (int o = 0; o < 8; o++) {
            int col = cbase + o * 8;
            int r0 = rbase + mt * 16;
            int r1 = r0 + 8;
            if (HALF_OUT) {
                *(uint32_t*)&Ch[(size_t)r0 * N + col] = packh(c[mt][o][0], c[mt][o][1]);
                *(uint32_t*)&Ch[(size_t)r1 * N + col] = packh(c[mt][o][2], c[mt][o][3]);
            } else {
                *(float2*)&Cout[(size_t)r0 * N + col] = make_float2(c[mt][o][0], c[mt][o][1]);
                *(float2*)&Cout[(size_t)r1 * N + col] = make_float2(c[mt][o][2], c[mt][o][3]);
            }
        }
    }
}

// ---------------------------------------------------------------------------
// Causal flash attention, fp16, persistent work-stealing, fixed-max softmax
// p = 2^(s*scale)  (bias 0: args small -> tight fp16 rounding; no overflow:
// 10-sigma score -> p ~ 2.2e4 < 65504; O and l accumulate fp32, ratio exact).
// Tasks: 512 = (head, q-tile), heavy q-tiles first; grid 304 persistent CTAs
// pull tasks from g_task_ctr (reset each replay by cvt_all_kernel).
// Block: 128 threads (4 warps), warp owns 32 q-rows.  2 CTAs/SM.
// l accumulated via MMA against an all-ones B fragment.
// ---------------------------------------------------------------------------
#define AQ  0
#define AKV 16384
#define KVB 16384
#define ATTN_SMEM (AKV + 3 * KVB + 1024)
#define N_TASKS (H_NUM * (T_SEQ / 128))      // 512

// log2(e) / sqrt(64)
#define QK_SCALE 0.1803368801111244f

__global__ __launch_bounds__(128, 2)
void attn_kernel()
{
    extern __shared__ char smraw[];
    __shared__ int s_task;
    const uint32_t sb = (s2u(smraw) + 1023u) & ~1023u;
    const int tid  = threadIdx.x;
    const int w    = tid >> 5;
    const int lane = tid & 31;
    const int rA   = lane >> 2;
    const uint32_t one2 = 0x3C003C00u;      // half2(1, 1)

    for (;;) {
        if (tid == 0) s_task = atomicAdd(&g_task_ctr, 1);
        __syncthreads();                     // broadcast + protect smem reuse
        const int task = s_task;
        if (task >= N_TASKS) break;
        const int h  = task & 15;
        const int qt = 31 - (task >> 4);     // heavy tiles first
        const int q0 = qt * 128;
        const int ntiles = 2 * qt + 2;

        auto load_kv = [&](int buf, int k0) {
            const uint32_t b0 = sb + AKV + buf * KVB;
#pragma unroll
            for (int it = 0; it < 8; it++) {
                int idx = tid + it * 128;       // 0..1023
                int arr = idx >> 9;             // 0:K 1:V
                int rem = idx & 511;
                int r = rem >> 3, q = rem & 7;
                uint32_t so = SW128(r * 128 + q * 16) + arr * 8192;
                size_t go = (size_t)(k0 + r) * F_DIM + (arr ? 2 * C_DIM : C_DIM) + h * 64 + q * 8;
                CP16(b0 + so, (const void*)(g_qkv + go));
            }
            CPCOMMIT();
        };

        load_kv(0, 0);

        // ---- stage Q tile (128 rows) ----
#pragma unroll
        for (int it = 0; it < 8; it++) {
            int idx = tid + it * 128;
            int r = idx >> 3, q = idx & 7;
            size_t go = (size_t)(q0 + r) * F_DIM + h * 64 + q * 8;
            uint32_t so = SW128(r * 128 + q * 16);
            uint4 vh = *(const uint4*)&g_qkv[go];
            asm volatile("st.shared.v4.b32 [%0],{%1,%2,%3,%4};"
                         :: "r"(sb + AQ + so), "r"(vh.x), "r"(vh.y), "r"(vh.z), "r"(vh.w));
        }
        __syncthreads();

        uint32_t qh[4][2][4];
#pragma unroll
        for (int ks = 0; ks < 4; ks++)
#pragma unroll
            for (int mt = 0; mt < 2; mt++) {
                uint32_t ro = (w * 32 + mt * 16 + (lane & 15)) * 128 + ks * 32 + (lane >> 4) * 16;
                ldsm4(qh[ks][mt], sb + AQ + SW128(ro));
            }

        float o[2][8][4];
        float lacc[2][4];
#pragma unroll
        for (int mt = 0; mt < 2; mt++) {
#pragma unroll
            for (int d = 0; d < 8; d++)
#pragma unroll
                for (int e = 0; e < 4; e++) o[mt][d][e] = 0.f;
#pragma unroll
            for (int e = 0; e < 4; e++) lacc[mt][e] = 0.f;
        }

        const int wrow_min = q0 + w * 32;
        const int wrow_max = wrow_min + 31;

        for (int j = 0; j < ntiles; j++) {
            const int k0 = j * 64;
            if (j + 1 < ntiles) load_kv((j + 1) % 3, (j + 1) * 64);
            if (j + 1 < ntiles) CPWAIT1(); else CPWAIT0();
            __syncthreads();

            if (k0 > wrow_max) continue;

            const uint32_t kvb = sb + AKV + (j % 3) * KVB;

            // ---- S = Q K^T ----
            float s[2][8][4];
#pragma unroll
            for (int mt = 0; mt < 2; mt++)
#pragma unroll
                for (int ot = 0; ot < 8; ot++)
#pragma unroll
                    for (int e = 0; e < 4; e++) s[mt][ot][e] = 0.f;
#pragma unroll
            for (int ks = 0; ks < 4; ks++) {
                uint32_t kh[4][4];
#pragma unroll
                for (int nt = 0; nt < 4; nt++) {
                    uint32_t ro = (nt * 16 + (lane & 15)) * 128 + ks * 32 + (lane >> 4) * 16;
                    ldsm4(kh[nt], kvb + SW128(ro));
                }
#pragma unroll
                for (int mt = 0; mt < 2; mt++)
#pragma unroll
                    for (int nt = 0; nt < 4; nt++) {
                        mma16816(s[mt][2 * nt],     qh[ks][mt], kh[nt][0], kh[nt][2]);
                        mma16816(s[mt][2 * nt + 1], qh[ks][mt], kh[nt][1], kh[nt][3]);
                    }
            }

            // ---- fixed-max softmax: p = 2^(s*scale), mask -> 0 ----
            const bool need_mask = (k0 + 63 > wrow_min);
            uint32_t p01[2][8], p23[2][8];
#pragma unroll
            for (int mt = 0; mt < 2; mt++) {
#pragma unroll
                for (int ot = 0; ot < 8; ot++) {
                    float v0 = s[mt][ot][0] * QK_SCALE;
                    float v1 = s[mt][ot][1] * QK_SCALE;
                    float v2 = s[mt][ot][2] * QK_SCALE;
                    float v3 = s[mt][ot][3] * QK_SCALE;
                    if (need_mask) {
                        int n = k0 + ot * 8 + (lane & 3) * 2;
                        int r0 = wrow_min + mt * 16 + rA;
                        int r1 = r0 + 8;
                        if (n > r0)     v0 = -1e30f;
                        if (n + 1 > r0) v1 = -1e30f;
                        if (n > r1)     v2 = -1e30f;
                        if (n + 1 > r1) v3 = -1e30f;
                    }
                    p01[mt][ot] = h2e2(v0, v1);
                    p23[mt][ot] = h2e2(v2, v3);
                }
            }

            // ---- O += P V,  l += P·1 ----
#pragma unroll
            for (int kt = 0; kt < 4; kt++) {
                uint32_t vh[4][4];
#pragma unroll
                for (int dt = 0; dt < 4; dt++) {
                    uint32_t ro = (kt * 16 + (lane & 15)) * 128 + dt * 32 + (lane >> 4) * 16;
                    ldsm4t(vh[dt], kvb + 8192 + SW128(ro));
                }
#pragma unroll
                for (int mt = 0; mt < 2; mt++) {
                    uint32_t ap[4] = { p01[mt][2 * kt], p23[mt][2 * kt],
                                       p01[mt][2 * kt + 1], p23[mt][2 * kt + 1] };
                    mma16816(lacc[mt], ap, one2, one2);
#pragma unroll
                    for (int dt = 0; dt < 4; dt++) {
                        mma16816(o[mt][2 * dt],     ap, vh[dt][0], vh[dt][1]);
                        mma16816(o[mt][2 * dt + 1], ap, vh[dt][2], vh[dt][3]);
                    }
                }
            }
        }

        // ---- finalize (l fully reduced by the MMA contraction) ----
#pragma unroll
        for (int mt = 0; mt < 2; mt++) {
            const float i0 = 1.f / lacc[mt][0], i1 = 1.f / lacc[mt][2];
            const int row0 = q0 + w * 32 + mt * 16 + rA;
            const int cb   = h * 64 + (lane & 3) * 2;
#pragma unroll
            for (int d = 0; d < 8; d++) {
                int col = cb + d * 8;
                *(uint32_t*)&g_y[(size_t)row0 * C_DIM + col] =
                    packh(o[mt][d][0] * i0, o[mt][d][1] * i0);
                *(uint32_t*)&g_y[(size_t)(row0 + 8) * C_DIM + col] =
                    packh(o[mt][d][2] * i1, o[mt][d][3] * i1);
            }
        }
    }
}

// ---------------------------------------------------------------------------
extern "C" void kernel_launch(void* const* d_in, const int* in_sizes, int n_in,
                              void* d_out, int out_size)
{
    const float* x      = (const float*)d_in[0];
    const float* w_attn = (const float*)d_in[1];
    const float* w_proj = (const float*)d_in[2];
    float* out = (float*)d_out;
    (void)in_sizes; (void)n_in; (void)out_size;

    cudaFuncSetAttribute(gemm_kernel<true>,
                         cudaFuncAttributeMaxDynamicSharedMemorySize, GEMM_SMEM);
    cudaFuncSetAttribute(gemm_kernel<false>,
                         cudaFuncAttributeMaxDynamicSharedMemorySize, GEMM_SMEM);
    cudaFuncSetAttribute(attn_kernel,
                         cudaFuncAttributeMaxDynamicSharedMemorySize, ATTN_SMEM);

    void *p_x, *p_wa, *p_wp, *p_qkv, *p_y;
    cudaGetSymbolAddress(&p_x, g_x);
    cudaGetSymbolAddress(&p_wa, g_wa);
    cudaGetSymbolAddress(&p_wp, g_wp);
    cudaGetSymbolAddress(&p_qkv, g_qkv);
    cudaGetSymbolAddress(&p_y, g_y);

    // 1) convert all inputs to fp16 + reset attention work counter
    cvt_all_kernel<<<8192, 256>>>(x, w_attn, w_proj);

    // 2) qkv = x @ w_attn^T  -> fp16
    gemm_kernel<true><<<dim3(F_DIM / 256, T_SEQ / 128), 256, GEMM_SMEM>>>(
        (const __half*)p_x, (const __half*)p_wa,
        nullptr, (__half*)p_qkv, C_DIM, F_DIM);

    // 3) persistent work-stealing causal attention -> fp16 y
    attn_kernel<<<304, 128, ATTN_SMEM>>>();

    // 4) out = y @ w_proj^T  (fp32 output)
    gemm_kernel<false><<<dim3(C_DIM / 256, T_SEQ / 128), 256, GEMM_SMEM>>>(
        (const __half*)p_y, (const __half*)p_wp,
        out, nullptr, C_DIM, C_DIM);
}